// round 6
// baseline (speedup 1.0000x reference)
#include <cuda_runtime.h>
#include <cstdint>

// Problem constants
#define BATCH   512
#define DIMC    64
#define BOOK    1024
#define EMB     64
#define CWDIM   (DIMC * EMB)            // 4096

// Output layout (floats): cw | one_hot | new_codebook | new_ema
#define CW_OFF    0
#define CW_SIZE   (BATCH * CWDIM)
#define OH_OFF    (CW_OFF + CW_SIZE)
#define OH_SIZE   (BATCH * DIMC * BOOK)              // 33,554,432
#define NCB_OFF   (OH_OFF + OH_SIZE)
#define NCB_SIZE  (DIMC * BOOK * EMB)                // 4,194,304
#define NEMA_OFF  (NCB_OFF + NCB_SIZE)
#define NEMA_SIZE (DIMC * BOOK)

#define TAU 0.05f
#define QS  2048.0f

// Scratch: int8 2-digit quantization packed [hi(64)|lo(64)] per row
__device__ int8_t g_qx[DIMC][BATCH][128];     // 4.2 MB
__device__ int8_t g_qc[DIMC][BOOK][128];      // 8.4 MB
__device__ float  g_bsq[DIMC * BOOK];
__device__ float4 g_top[BATCH * DIMC * 16];   // (b1, b2, k1bits, -) per N-tile

static __device__ __forceinline__ uint32_t smem_u32(const void* p) {
    uint32_t a;
    asm("{ .reg .u64 t; cvta.to.shared.u64 t, %1; cvt.u32.u64 %0, t; }"
        : "=r"(a) : "l"(p));
    return a;
}

#define LDSM_X4(r0, r1, r2, r3, a)                                       \
    asm volatile("ldmatrix.sync.aligned.m8n8.x4.shared.b16 "             \
                 "{%0,%1,%2,%3}, [%4];"                                  \
                 : "=r"(r0), "=r"(r1), "=r"(r2), "=r"(r3) : "r"(a))

#define IMMA16832(c, a, b)                                               \
    asm volatile("mma.sync.aligned.m16n8k32.row.col.s32.s8.s8.s32 "      \
                 "{%0,%1,%2,%3}, {%4,%5,%6,%7}, {%8,%9}, {%0,%1,%2,%3};" \
                 : "+r"((c)[0]), "+r"((c)[1]), "+r"((c)[2]), "+r"((c)[3])\
                 : "r"((a)[0]), "r"((a)[1]), "r"((a)[2]), "r"((a)[3]),   \
                   "r"((b)[0]), "r"((b)[1]))

// ---------------------------------------------------------------------------
// Kernel 0: int8 2-digit quantization of x and codebook + exact |c|^2.
// One warp per 64-element row; lane handles 2 elements.
// ---------------------------------------------------------------------------
static __device__ __forceinline__ void quant2(float v, int8_t& hi, int8_t& lo) {
    int q = __float2int_rn(v * QS);
    q = max(-16256, min(16256, q));
    int h = (q + 64) >> 7;
    hi = (int8_t)h;
    lo = (int8_t)(q - (h << 7));
}

__global__ void __launch_bounds__(256)
quant_kernel(const float* __restrict__ x, const float* __restrict__ cb)
{
    int gw   = (blockIdx.x * 256 + threadIdx.x) >> 5;
    int lane = threadIdx.x & 31;
    int e0   = lane * 2;

    if (gw < DIMC * BATCH) {
        int d = gw >> 9, b = gw & 511;
        float2 v = *(const float2*)(x + (size_t)b * CWDIM + d * EMB + e0);
        int8_t h0, l0, h1, l1;
        quant2(v.x, h0, l0);
        quant2(v.y, h1, l1);
        int8_t* row = &g_qx[d][b][0];
        *(char2*)(row + e0)      = make_char2(h0, h1);
        *(char2*)(row + 64 + e0) = make_char2(l0, l1);
    } else {
        int r = gw - DIMC * BATCH;                 // d*1024 + k
        float2 v = *(const float2*)(cb + (size_t)r * EMB + e0);
        int8_t h0, l0, h1, l1;
        quant2(v.x, h0, l0);
        quant2(v.y, h1, l1);
        int8_t* row = &g_qc[0][0][0] + (size_t)r * 128;
        *(char2*)(row + e0)      = make_char2(h0, h1);
        *(char2*)(row + 64 + e0) = make_char2(l0, l1);
        float s = v.x * v.x + v.y * v.y;
        #pragma unroll
        for (int off = 16; off; off >>= 1)
            s += __shfl_xor_sync(0xffffffffu, s, off);
        if (lane == 0) g_bsq[r] = s;
    }
}

// ---------------------------------------------------------------------------
// Kernel 1: CTA tile 128 rows x 64 codes per d. 8 warps (4M x 2N), warp tile
// 32x32. Exact integer dot via 4 IMMA digit passes (hh*16384, hl*128, lh*128,
// ll*1), each flushed into fp32. Fused one_hot zero + ncb/nema init.
// Epilogue: per-row top-2 -> g_top[16 tiles].
// SMEM rows: 128B data + 16B pad (stride 144) => conflict-free ldmatrix.
// ---------------------------------------------------------------------------
#define STRIDE   144
#define OFF_BSM  (128 * STRIDE)               // A: 18432
#define OFF_BSQ2 (OFF_BSM + 64 * STRIDE)      // 27648
#define SMEM_REQ (OFF_BSQ2 + 256)             // 27904

__global__ void __launch_bounds__(256, 2)
gemm_kernel(const float* __restrict__ cbin, const float* __restrict__ ema,
            float* __restrict__ out)
{
    extern __shared__ char smp[];
    const uint32_t smA = smem_u32(smp);
    const uint32_t smB = smA + OFF_BSM;
    float* bsqs = (float*)(smp + OFF_BSQ2);

    const int t = threadIdx.x, warp = t >> 5, lane = t & 31;
    const int wm = warp >> 1, wn = warp & 1;
    const int mtc = blockIdx.x & 3, ntc = blockIdx.x >> 2;   // 4 x 16
    const int d  = blockIdx.y;
    const int b0 = mtc * 128, k0 = ntc * 64;
    const int blk = d * 64 + blockIdx.x;     // 0..4095

    // ---- fused output prep (fire-and-forget) ----
    {
        float4 z = make_float4(0.f, 0.f, 0.f, 0.f);
        float4* oh4 = (float4*)(out + OH_OFF);
        size_t base = (size_t)blk * 2048;
        #pragma unroll
        for (int it = 0; it < 8; ++it)
            oh4[base + t + it * 256] = z;

        const float4* cb4 = (const float4*)cbin;
        float4* ncb4 = (float4*)(out + NCB_OFF);
        size_t cb0 = (size_t)blk * 256 + t;
        float4 v = cb4[cb0];
        v.x *= 0.999f; v.y *= 0.999f; v.z *= 0.999f; v.w *= 0.999f;
        ncb4[cb0] = v;

        if (t < 4) {
            const float4* em4 = (const float4*)ema;
            float4* ne4 = (float4*)(out + NEMA_OFF);
            size_t eb = (size_t)blk * 4 + t;
            float4 e = em4[eb];
            e.x *= 0.999f; e.y *= 0.999f; e.z *= 0.999f; e.w *= 0.999f;
            ne4[eb] = e;
        }
    }

    // ---- load A (128 x rows) and B (64 code rows), 128B each, + bsq ----
    #pragma unroll
    for (int it = 0; it < 4; ++it) {
        int idx = t + it * 256;          // 0..1023
        int row = idx >> 3, seg = idx & 7;
        uint4 va = *(const uint4*)(&g_qx[d][b0 + row][seg * 16]);
        *(uint4*)(smp + row * STRIDE + seg * 16) = va;
    }
    #pragma unroll
    for (int it = 0; it < 2; ++it) {
        int idx = t + it * 256;          // 0..511
        int row = idx >> 3, seg = idx & 7;
        uint4 vb = *(const uint4*)(&g_qc[d][k0 + row][seg * 16]);
        *(uint4*)(smp + OFF_BSM + row * STRIDE + seg * 16) = vb;
    }
    if (t < 64) bsqs[t] = g_bsq[d * BOOK + k0 + t];
    __syncthreads();

    // ---- IMMA mainloop: 4 digit passes x 2 k32-steps ----
    float accf[2][4][4];
    #pragma unroll
    for (int i = 0; i < 2; ++i)
        #pragma unroll
        for (int j = 0; j < 4; ++j)
            #pragma unroll
            for (int q = 0; q < 4; ++q) accf[i][j][q] = 0.f;

    const int lr = (lane & 7) + ((lane >> 3) & 1) * 8;
    const int ka = ((lane >> 4) & 1) * 16;
    const int nr = (lane & 7) + ((lane >> 4) & 1) * 8;
    const int kb = ((lane >> 3) & 1) * 16;

    const uint32_t aBase = smA + (wm * 32 + lr) * STRIDE + ka;
    const uint32_t bBase = smB + (wn * 32 + nr) * STRIDE + kb;

    #pragma unroll
    for (int ad = 0; ad < 2; ++ad) {
        uint32_t af[2][2][4];   // [ks][mt][4]
        #pragma unroll
        for (int ks = 0; ks < 2; ++ks)
            #pragma unroll
            for (int mt = 0; mt < 2; ++mt)
                LDSM_X4(af[ks][mt][0], af[ks][mt][1],
                        af[ks][mt][2], af[ks][mt][3],
                        aBase + mt * (16 * STRIDE) + ad * 64 + ks * 32);
        #pragma unroll
        for (int bd = 0; bd < 2; ++bd) {
            int accS[2][4][4];
            #pragma unroll
            for (int i = 0; i < 2; ++i)
                #pragma unroll
                for (int j = 0; j < 4; ++j)
                    #pragma unroll
                    for (int q = 0; q < 4; ++q) accS[i][j][q] = 0;

            #pragma unroll
            for (int ks = 0; ks < 2; ++ks) {
                uint32_t bf[4][2];
                #pragma unroll
                for (int np = 0; np < 2; ++np)
                    LDSM_X4(bf[np * 2][0], bf[np * 2][1],
                            bf[np * 2 + 1][0], bf[np * 2 + 1][1],
                            bBase + np * (16 * STRIDE) + bd * 64 + ks * 32);
                #pragma unroll
                for (int mt = 0; mt < 2; ++mt)
                    #pragma unroll
                    for (int nt = 0; nt < 4; ++nt)
                        IMMA16832(accS[mt][nt], af[ks][mt], bf[nt]);
            }
            // flush: weight = 16384 (hh), 128 (hl/lh), 1 (ll)
            const float w = (ad == 0 && bd == 0) ? 16384.f
                          : (ad == bd ? 1.f : 128.f);
            #pragma unroll
            for (int mt = 0; mt < 2; ++mt)
                #pragma unroll
                for (int nt = 0; nt < 4; ++nt)
                    #pragma unroll
                    for (int q = 0; q < 4; ++q)
                        accf[mt][nt][q] = fmaf(w, __int2float_rn(accS[mt][nt][q]),
                                               accf[mt][nt][q]);
        }
    }

    __syncthreads();   // A region about to be reused as sm_top
    float4* sm_top = (float4*)smp;   // [128 rows][2 wn]

    // ---- epilogue: dist = bsq - 2*D/QS^2, per-row top-2 ----
    const float SC = -0x1p-21f;     // -2 / 2048^2
    #pragma unroll
    for (int mt = 0; mt < 2; ++mt) {
        #pragma unroll
        for (int h = 0; h < 2; ++h) {
            int row = wm * 32 + mt * 16 + (lane >> 2) + h * 8;
            float b1 = 3.4e38f, b2 = 3.4e38f;
            int   k1 = 0;
            #pragma unroll
            for (int nt = 0; nt < 4; ++nt) {
                #pragma unroll
                for (int j = 0; j < 2; ++j) {
                    int col = wn * 32 + nt * 8 + (lane & 3) * 2 + j;
                    float dist = fmaf(accf[mt][nt][h * 2 + j], SC, bsqs[col]);
                    if (dist < b1) { b2 = b1; b1 = dist; k1 = k0 + col; }
                    else if (dist < b2) { b2 = dist; }
                }
            }
            #pragma unroll
            for (int off = 1; off <= 2; off <<= 1) {
                float ob1 = __shfl_xor_sync(0xffffffffu, b1, off);
                int   ok1 = __shfl_xor_sync(0xffffffffu, k1, off);
                float ob2 = __shfl_xor_sync(0xffffffffu, b2, off);
                if (ob1 < b1 || (ob1 == b1 && ok1 < k1)) {
                    b2 = fminf(ob2, b1); b1 = ob1; k1 = ok1;
                } else {
                    b2 = fminf(b2, ob1);
                }
            }
            if ((lane & 3) == 0)
                sm_top[row * 2 + wn] =
                    make_float4(b1, b2, __int_as_float(k1), 0.f);
        }
    }
    __syncthreads();

    if (t < 128) {
        float4 e0 = sm_top[t * 2 + 0];
        float4 e1 = sm_top[t * 2 + 1];
        float b1, b2; int k1;
        int ek0 = __float_as_int(e0.z), ek1 = __float_as_int(e1.z);
        if (e1.x < e0.x || (e1.x == e0.x && ek1 < ek0)) {
            b1 = e1.x; k1 = ek1; b2 = fminf(e1.y, e0.x);
        } else {
            b1 = e0.x; k1 = ek0; b2 = fminf(e0.y, e1.x);
        }
        g_top[((size_t)(b0 + t) * DIMC + d) * 16 + ntc] =
            make_float4(b1, b2, __int_as_float(k1), 0.f);
    }
}

// ---------------------------------------------------------------------------
// Kernel 2: merge top-2 tiles -> argmin (exact fp32 repair when gap < TAU),
// then gather cw, set one_hot ones, EMA scatter-adds. One warp per (b,d).
// ---------------------------------------------------------------------------
__global__ void __launch_bounds__(256)
scatter_kernel(const float* __restrict__ x, const float* __restrict__ cb,
               const float* __restrict__ ema, float* __restrict__ out)
{
    const float GAINF = (float)(1.0 - 0.999);
    const float EPSF  = 1e-6f;
    float* cw   = out + CW_OFF;
    float* oh   = out + OH_OFF;
    float* ncb  = out + NCB_OFF;
    float* nema = out + NEMA_OFF;

    int b    = blockIdx.x;
    int warp = threadIdx.x >> 5;
    int lane = threadIdx.x & 31;

    #pragma unroll 1
    for (int dd = 0; dd < 8; ++dd) {
        int d = warp * 8 + dd;

        // merge the 16 N-tile top-2 entries
        float b1 = 3.4e38f, b2 = 3.4e38f;
        int   k1 = 0x7fffffff;
        if (lane < 16) {
            float4 e = g_top[((size_t)b * DIMC + d) * 16 + lane];
            b1 = e.x; b2 = e.y; k1 = __float_as_int(e.z);
        }
        #pragma unroll
        for (int off = 1; off <= 8; off <<= 1) {
            float ob1 = __shfl_xor_sync(0xffffffffu, b1, off);
            int   ok1 = __shfl_xor_sync(0xffffffffu, k1, off);
            float ob2 = __shfl_xor_sync(0xffffffffu, b2, off);
            if (ob1 < b1 || (ob1 == b1 && ok1 < k1)) {
                b2 = fminf(ob2, b1); b1 = ob1; k1 = ok1;
            } else {
                b2 = fminf(b2, ob1);
            }
        }
        float gap = __shfl_sync(0xffffffffu, b2 - b1, 0);
        int   k   = __shfl_sync(0xffffffffu, k1, 0);

        if (gap < TAU) {
            // exact fp32 re-argmin over all 1024 codes for this (b,d)
            const float* xr = x + (size_t)b * CWDIM + d * EMB;
            float bd = 3.4e38f;
            int   bk = 0;
            for (int i = 0; i < 32; ++i) {
                int kc = i * 32 + lane;
                const float* cp = cb + ((size_t)d * BOOK + kc) * EMB;
                float dot = 0.f;
                #pragma unroll
                for (int e = 0; e < EMB; ++e)
                    dot = fmaf(xr[e], cp[e], dot);
                float dist = fmaf(-2.f, dot, g_bsq[d * BOOK + kc]);
                if (dist < bd) { bd = dist; bk = kc; }
            }
            #pragma unroll
            for (int off = 16; off; off >>= 1) {
                float od = __shfl_xor_sync(0xffffffffu, bd, off);
                int   ok = __shfl_xor_sync(0xffffffffu, bk, off);
                if (od < bd || (od == bd && ok < bk)) { bd = od; bk = ok; }
            }
            k = bk;
        }

        float g = GAINF / (ema[d * BOOK + k] + EPSF);

        size_t co = ((size_t)d * BOOK + k) * EMB + 2 * lane;
        size_t xo = (size_t)b * CWDIM + d * EMB + 2 * lane;
        float2 c2 = *(const float2*)(cb + co);
        float2 x2 = *(const float2*)(x + xo);

        float2 w;
        w.x = x2.x + (c2.x - x2.x);
        w.y = x2.y + (c2.y - x2.y);
        *(float2*)(cw + xo) = w;

        atomicAdd(ncb + co,     g * x2.x);
        atomicAdd(ncb + co + 1, g * x2.y);

        if (lane == 0) {
            oh[(size_t)b * (DIMC * BOOK) + (size_t)d * BOOK + k] = 1.0f;
            atomicAdd(nema + d * BOOK + k, GAINF);
        }
    }
}

// ---------------------------------------------------------------------------
extern "C" void kernel_launch(void* const* d_in, const int* in_sizes, int n_in,
                              void* d_out, int out_size)
{
    (void)in_sizes; (void)n_in; (void)out_size;
    const float* x   = (const float*)d_in[0];
    const float* cb  = (const float*)d_in[1];
    const float* ema = (const float*)d_in[2];
    float* out = (float*)d_out;

    cudaFuncSetAttribute(gemm_kernel,
                         cudaFuncAttributeMaxDynamicSharedMemorySize, SMEM_REQ);

    quant_kernel<<<12288, 256>>>(x, cb);
    dim3 grid(64, 64);   // (4 M-tiles x 16 N-tiles), 64 dims
    gemm_kernel<<<grid, 256, SMEM_REQ>>>(cb, ema, out);
    scatter_kernel<<<BATCH, 256>>>(x, cb, ema, out);
}

// round 7
// speedup vs baseline: 1.1000x; 1.1000x over previous
#include <cuda_runtime.h>
#include <cuda_bf16.h>
#include <cstdint>

// Problem constants
#define BATCH   512
#define DIMC    64
#define BOOK    1024
#define EMB     64
#define CWDIM   (DIMC * EMB)            // 4096

// Output layout (floats): cw | one_hot | new_codebook | new_ema
#define CW_OFF    0
#define CW_SIZE   (BATCH * CWDIM)
#define OH_OFF    (CW_OFF + CW_SIZE)
#define OH_SIZE   (BATCH * DIMC * BOOK)              // 33,554,432
#define NCB_OFF   (OH_OFF + OH_SIZE)
#define NCB_SIZE  (DIMC * BOOK * EMB)                // 4,194,304
#define NEMA_OFF  (NCB_OFF + NCB_SIZE)
#define NEMA_SIZE (DIMC * BOOK)

#define TAU 0.02f

// Scratch: bf16 2-term splits packed [h(64)|l(64)] per row
__device__ __nv_bfloat16 g_x2[DIMC][BATCH][128];   // 8.4 MB
__device__ __nv_bfloat16 g_c2[DIMC][BOOK][128];    // 16.8 MB
__device__ float  g_bsq[DIMC * BOOK];
__device__ float4 g_top[BATCH * DIMC * 8];         // (b1,b2,k1bits,-) per N-tile

static __device__ __forceinline__ uint32_t smem_u32(const void* p) {
    uint32_t a;
    asm("{ .reg .u64 t; cvta.to.shared.u64 t, %1; cvt.u32.u64 %0, t; }"
        : "=r"(a) : "l"(p));
    return a;
}

#define LDSM_X4(r0, r1, r2, r3, a)                                       \
    asm volatile("ldmatrix.sync.aligned.m8n8.x4.shared.b16 "             \
                 "{%0,%1,%2,%3}, [%4];"                                  \
                 : "=r"(r0), "=r"(r1), "=r"(r2), "=r"(r3) : "r"(a))

#define MMA16816(c, a, b)                                                \
    asm volatile("mma.sync.aligned.m16n8k16.row.col.f32.bf16.bf16.f32 "  \
                 "{%0,%1,%2,%3}, {%4,%5,%6,%7}, {%8,%9}, {%0,%1,%2,%3};" \
                 : "+f"((c)[0]), "+f"((c)[1]), "+f"((c)[2]), "+f"((c)[3])\
                 : "r"((a)[0]), "r"((a)[1]), "r"((a)[2]), "r"((a)[3]),   \
                   "r"((b)[0]), "r"((b)[1]))

// ---------------------------------------------------------------------------
// Kernel 0: bf16 2-term splits of x and codebook (packed [h|l]) + |c|^2.
// One warp per 64-element row; lane handles 2 elements.
// ---------------------------------------------------------------------------
__global__ void __launch_bounds__(256)
quant_kernel(const float* __restrict__ x, const float* __restrict__ cb)
{
    int gw   = (blockIdx.x * 256 + threadIdx.x) >> 5;
    int lane = threadIdx.x & 31;
    int e0   = lane * 2;

    if (gw < DIMC * BATCH) {
        int d = gw >> 9, b = gw & 511;
        float2 v = *(const float2*)(x + (size_t)b * CWDIM + d * EMB + e0);
        __nv_bfloat16 h0 = __float2bfloat16_rn(v.x);
        __nv_bfloat16 l0 = __float2bfloat16_rn(v.x - __bfloat162float(h0));
        __nv_bfloat16 h1 = __float2bfloat16_rn(v.y);
        __nv_bfloat16 l1 = __float2bfloat16_rn(v.y - __bfloat162float(h1));
        __nv_bfloat162* row = (__nv_bfloat162*)&g_x2[d][b][0];
        __nv_bfloat162 th; th.x = h0; th.y = h1;
        __nv_bfloat162 tl; tl.x = l0; tl.y = l1;
        row[lane]      = th;
        row[32 + lane] = tl;
    } else {
        int r = gw - DIMC * BATCH;                 // d*1024 + k
        float2 v = *(const float2*)(cb + (size_t)r * EMB + e0);
        __nv_bfloat16 h0 = __float2bfloat16_rn(v.x);
        __nv_bfloat16 l0 = __float2bfloat16_rn(v.x - __bfloat162float(h0));
        __nv_bfloat16 h1 = __float2bfloat16_rn(v.y);
        __nv_bfloat16 l1 = __float2bfloat16_rn(v.y - __bfloat162float(h1));
        __nv_bfloat162* row = (__nv_bfloat162*)(&g_c2[0][0][0] + (size_t)r * 128);
        __nv_bfloat162 th; th.x = h0; th.y = h1;
        __nv_bfloat162 tl; tl.x = l0; tl.y = l1;
        row[lane]      = th;
        row[32 + lane] = tl;
        float s = v.x * v.x + v.y * v.y;
        #pragma unroll
        for (int off = 16; off; off >>= 1)
            s += __shfl_xor_sync(0xffffffffu, s, off);
        if (lane == 0) g_bsq[r] = s;
    }
}

// ---------------------------------------------------------------------------
// Kernel 1: per (d, 128 rows, 128 codes) tile. Exact bf16 2-term dot via
// aligned pass (hh+ll) + k-rotated pass (hl+lh). Structure cloned from the
// R3 config that hit the HMMA rate: 8 warps (2M x 4N), warp tile 64x32,
// stride-272 smem, upfront fused one_hot zero + ncb/nema DECAY-init.
// Epilogue: per-row top-2 -> g_top[8 tiles].
// ---------------------------------------------------------------------------
#define STRIDE   272
#define OFF_BSM  (128 * STRIDE)            // 34816
#define OFF_BSQ2 (2 * 128 * STRIDE)        // 69632
#define SMEM_REQ (OFF_BSQ2 + 512)          // 70144

__global__ void __launch_bounds__(256, 2)
gemm_kernel(const float* __restrict__ cbin, const float* __restrict__ ema,
            float* __restrict__ out)
{
    extern __shared__ char smp[];
    const uint32_t smA = smem_u32(smp);
    const uint32_t smB = smA + OFF_BSM;
    float* bsqs = (float*)(smp + OFF_BSQ2);

    const int t = threadIdx.x, warp = t >> 5, lane = t & 31;
    const int wm = warp >> 2, wn = warp & 3;
    const int mtc = blockIdx.x & 3, ntc = blockIdx.x >> 2;   // 4 x 8
    const int d  = blockIdx.y;
    const int b0 = mtc * 128, k0 = ntc * 128;
    const int blk = d * 32 + blockIdx.x;     // 0..2047

    // ---- fused output prep (fire-and-forget; hides under MMAs) ----
    {
        float4 z = make_float4(0.f, 0.f, 0.f, 0.f);
        float4* oh4 = (float4*)(out + OH_OFF);
        size_t base = (size_t)blk * 4096;
        #pragma unroll 4
        for (int it = 0; it < 16; ++it)
            oh4[base + t + it * 256] = z;

        const float4* cb4 = (const float4*)cbin;
        float4* ncb4 = (float4*)(out + NCB_OFF);
        size_t cb0 = (size_t)blk * 512;
        #pragma unroll
        for (int it = 0; it < 2; ++it) {
            float4 v = cb4[cb0 + t + it * 256];
            v.x *= 0.999f; v.y *= 0.999f; v.z *= 0.999f; v.w *= 0.999f;
            ncb4[cb0 + t + it * 256] = v;
        }
        if (t < 8) {
            const float4* em4 = (const float4*)ema;
            float4* ne4 = (float4*)(out + NEMA_OFF);
            size_t eb = (size_t)blk * 8 + t;
            float4 v = em4[eb];
            v.x *= 0.999f; v.y *= 0.999f; v.z *= 0.999f; v.w *= 0.999f;
            ne4[eb] = v;
        }
    }

    // ---- load A (128 x rows) and B (128 code rows), 256B each, + bsq ----
    #pragma unroll
    for (int it = 0; it < 8; ++it) {
        int idx = t + it * 256;          // 0..2047
        int row = idx >> 4, seg = idx & 15;
        uint4 va = *(const uint4*)(&g_x2[d][b0 + row][seg * 8]);
        *(uint4*)(smp + row * STRIDE + seg * 16) = va;
        uint4 vb = *(const uint4*)(&g_c2[d][k0 + row][seg * 8]);
        *(uint4*)(smp + OFF_BSM + row * STRIDE + seg * 16) = vb;
    }
    if (t < 128) bsqs[t] = g_bsq[d * BOOK + k0 + t];
    __syncthreads();

    // ---- MMA mainloop: 2 passes (aligned, swapped) x 8 ksteps ----
    float acc[4][4][4];
    #pragma unroll
    for (int i = 0; i < 4; ++i)
        #pragma unroll
        for (int j = 0; j < 4; ++j)
            #pragma unroll
            for (int q = 0; q < 4; ++q) acc[i][j][q] = 0.f;

    const int lr = (lane & 7) + ((lane >> 3) & 1) * 8;
    const int ka = ((lane >> 4) & 1) * 16;
    const int nr = (lane & 7) + ((lane >> 4) & 1) * 8;
    const int kb = ((lane >> 3) & 1) * 16;

    const uint32_t aBase = smA + (wm * 64 + lr) * STRIDE + ka;
    const uint32_t bBase = smB + (wn * 32 + nr) * STRIDE + kb;

    #pragma unroll
    for (int v = 0; v < 2; ++v) {
        #pragma unroll
        for (int ks = 0; ks < 8; ++ks) {
            const int kk = (ks + v * 4) & 7;    // v=1: k-halves rotated
            uint32_t af[4][4];
            #pragma unroll
            for (int mt = 0; mt < 4; ++mt)
                LDSM_X4(af[mt][0], af[mt][1], af[mt][2], af[mt][3],
                        aBase + mt * (16 * STRIDE) + ks * 32);
            uint32_t bf[4][2];
            #pragma unroll
            for (int np = 0; np < 2; ++np)
                LDSM_X4(bf[np * 2][0], bf[np * 2][1],
                        bf[np * 2 + 1][0], bf[np * 2 + 1][1],
                        bBase + np * (16 * STRIDE) + kk * 32);
            #pragma unroll
            for (int mt = 0; mt < 4; ++mt)
                #pragma unroll
                for (int nt = 0; nt < 4; ++nt)
                    MMA16816(acc[mt][nt], af[mt], bf[nt]);
        }
    }

    __syncthreads();   // A region about to be reused as sm_top
    float4* sm_top = (float4*)smp;   // [128 rows][4 wn]

    // ---- epilogue: per-row top-2 (dist = bsq - 2*dot) ----
    #pragma unroll
    for (int mt = 0; mt < 4; ++mt) {
        #pragma unroll
        for (int h = 0; h < 2; ++h) {
            int row = wm * 64 + mt * 16 + (lane >> 2) + h * 8;
            float b1 = 3.4e38f, b2 = 3.4e38f;
            int   k1 = 0;
            #pragma unroll
            for (int nt = 0; nt < 4; ++nt) {
                #pragma unroll
                for (int j = 0; j < 2; ++j) {
                    int col = wn * 32 + nt * 8 + (lane & 3) * 2 + j;
                    float dist = fmaf(-2.f, acc[mt][nt][h * 2 + j], bsqs[col]);
                    if (dist < b1) { b2 = b1; b1 = dist; k1 = k0 + col; }
                    else if (dist < b2) { b2 = dist; }
                }
            }
            #pragma unroll
            for (int off = 1; off <= 2; off <<= 1) {
                float ob1 = __shfl_xor_sync(0xffffffffu, b1, off);
                int   ok1 = __shfl_xor_sync(0xffffffffu, k1, off);
                float ob2 = __shfl_xor_sync(0xffffffffu, b2, off);
                if (ob1 < b1 || (ob1 == b1 && ok1 < k1)) {
                    b2 = fminf(ob2, b1); b1 = ob1; k1 = ok1;
                } else {
                    b2 = fminf(b2, ob1);
                }
            }
            if ((lane & 3) == 0)
                sm_top[row * 4 + wn] =
                    make_float4(b1, b2, __int_as_float(k1), 0.f);
        }
    }
    __syncthreads();

    if (t < 128) {
        float b1 = 3.4e38f, b2 = 3.4e38f;
        int   k1 = 0x7fffffff;
        #pragma unroll
        for (int w = 0; w < 4; ++w) {
            float4 e = sm_top[t * 4 + w];
            int ek = __float_as_int(e.z);
            if (e.x < b1 || (e.x == b1 && ek < k1)) {
                b2 = fminf(e.y, b1); b1 = e.x; k1 = ek;
            } else {
                b2 = fminf(b2, e.x);
            }
        }
        g_top[((size_t)(b0 + t) * DIMC + d) * 8 + ntc] =
            make_float4(b1, b2, __int_as_float(k1), 0.f);
    }
}

// ---------------------------------------------------------------------------
// Kernel 2: merge top-2 tiles -> argmin (exact fp32 repair when gap < TAU),
// then gather cw, set one_hot ones, EMA scatter-adds. One warp per (b,d).
// ---------------------------------------------------------------------------
__global__ void __launch_bounds__(256)
scatter_kernel(const float* __restrict__ x, const float* __restrict__ cb,
               const float* __restrict__ ema, float* __restrict__ out)
{
    const float GAINF = (float)(1.0 - 0.999);
    const float EPSF  = 1e-6f;
    float* cw   = out + CW_OFF;
    float* oh   = out + OH_OFF;
    float* ncb  = out + NCB_OFF;
    float* nema = out + NEMA_OFF;

    int b    = blockIdx.x;
    int warp = threadIdx.x >> 5;
    int lane = threadIdx.x & 31;

    #pragma unroll 1
    for (int dd = 0; dd < 8; ++dd) {
        int d = warp * 8 + dd;

        // merge the 8 N-tile top-2 entries
        float b1 = 3.4e38f, b2 = 3.4e38f;
        int   k1 = 0x7fffffff;
        if (lane < 8) {
            float4 e = g_top[((size_t)b * DIMC + d) * 8 + lane];
            b1 = e.x; b2 = e.y; k1 = __float_as_int(e.z);
        }
        #pragma unroll
        for (int off = 1; off <= 4; off <<= 1) {
            float ob1 = __shfl_xor_sync(0xffffffffu, b1, off);
            int   ok1 = __shfl_xor_sync(0xffffffffu, k1, off);
            float ob2 = __shfl_xor_sync(0xffffffffu, b2, off);
            if (ob1 < b1 || (ob1 == b1 && ok1 < k1)) {
                b2 = fminf(ob2, b1); b1 = ob1; k1 = ok1;
            } else {
                b2 = fminf(b2, ob1);
            }
        }
        float gap = __shfl_sync(0xffffffffu, b2 - b1, 0);
        int   k   = __shfl_sync(0xffffffffu, k1, 0);

        if (gap < TAU) {
            // exact fp32 re-argmin over all 1024 codes for this (b,d)
            const float* xr = x + (size_t)b * CWDIM + d * EMB;
            float bd = 3.4e38f;
            int   bk = 0;
            for (int i = 0; i < 32; ++i) {
                int kc = i * 32 + lane;
                const float* cp = cb + ((size_t)d * BOOK + kc) * EMB;
                float dot = 0.f;
                #pragma unroll
                for (int e = 0; e < EMB; ++e)
                    dot = fmaf(xr[e], cp[e], dot);
                float dist = fmaf(-2.f, dot, g_bsq[d * BOOK + kc]);
                if (dist < bd) { bd = dist; bk = kc; }
            }
            #pragma unroll
            for (int off = 16; off; off >>= 1) {
                float od = __shfl_xor_sync(0xffffffffu, bd, off);
                int   ok = __shfl_xor_sync(0xffffffffu, bk, off);
                if (od < bd || (od == bd && ok < bk)) { bd = od; bk = ok; }
            }
            k = bk;
        }

        float g = GAINF / (ema[d * BOOK + k] + EPSF);

        size_t co = ((size_t)d * BOOK + k) * EMB + 2 * lane;
        size_t xo = (size_t)b * CWDIM + d * EMB + 2 * lane;
        float2 c2 = *(const float2*)(cb + co);
        float2 x2 = *(const float2*)(x + xo);

        float2 w;
        w.x = x2.x + (c2.x - x2.x);
        w.y = x2.y + (c2.y - x2.y);
        *(float2*)(cw + xo) = w;

        atomicAdd(ncb + co,     g * x2.x);
        atomicAdd(ncb + co + 1, g * x2.y);

        if (lane == 0) {
            oh[(size_t)b * (DIMC * BOOK) + (size_t)d * BOOK + k] = 1.0f;
            atomicAdd(nema + d * BOOK + k, GAINF);
        }
    }
}

// ---------------------------------------------------------------------------
extern "C" void kernel_launch(void* const* d_in, const int* in_sizes, int n_in,
                              void* d_out, int out_size)
{
    (void)in_sizes; (void)n_in; (void)out_size;
    const float* x   = (const float*)d_in[0];
    const float* cb  = (const float*)d_in[1];
    const float* ema = (const float*)d_in[2];
    float* out = (float*)d_out;

    cudaFuncSetAttribute(gemm_kernel,
                         cudaFuncAttributeMaxDynamicSharedMemorySize, SMEM_REQ);

    quant_kernel<<<12288, 256>>>(x, cb);
    dim3 grid(32, 64);   // (4 M-tiles x 8 N-tiles), 64 dims
    gemm_kernel<<<grid, 256, SMEM_REQ>>>(cb, ema, out);
    scatter_kernel<<<BATCH, 256>>>(x, cb, ema, out);
}

// round 8
// speedup vs baseline: 1.2081x; 1.0982x over previous
#include <cuda_runtime.h>
#include <cstdint>

// Problem constants
#define BATCH   512
#define DIMC    64
#define BOOK    1024
#define EMB     64
#define CWDIM   (DIMC * EMB)            // 4096

// Output layout (floats): cw | one_hot | new_codebook | new_ema
#define CW_OFF    0
#define CW_SIZE   (BATCH * CWDIM)                    // 2,097,152
#define OH_OFF    (CW_OFF + CW_SIZE)                 // 2,097,152
#define OH_SIZE   (BATCH * DIMC * BOOK)              // 33,554,432
#define NCB_OFF   (OH_OFF + OH_SIZE)                 // 35,651,584
#define NCB_SIZE  (DIMC * BOOK * EMB)                // 4,194,304
#define NEMA_OFF  (NCB_OFF + NCB_SIZE)               // 39,845,888
#define NEMA_SIZE (DIMC * BOOK)                      // 65,536

__device__ int g_idx[BATCH * DIMC];

// ---------------------------------------------------------------------------
// Kernel 1: fused (a) zero one_hot, (b) init new_codebook/new_ema with DECAY,
// (c) batched distance-argmin via f32x2 packed FMA.
//
// Grid: (4, 64) — blockIdx.x = 128-row tile of B, blockIdx.y = d. 256 thr.
// SMEM:
//   xs[e][row]    64 x 130 f32 (transposed x tile, 520B rows)   33280 B
//   csd[k][e]     128 x 65 float2 (codebook k-tile, DUPLICATED  66560 B
//                 (c,c) pairs; 520B rows -> conflict-free LDS.64)
//   bsq[1024]     |c|^2 for the whole d-slice                    4096 B
// Thread (tr,tc)=(t>>4,t&15): row pairs p=tr+16i (i<4) -> 8 rows;
// k = tc+16j (j<8) per 128-wide k tile. acc[4][8] f32x2 = 64 regs.
// Per e-iter: 4 LDS.64 (a2) + 8 LDS.64 (bb) + 32 FFMA2 = 64 MACs.
// ---------------------------------------------------------------------------
#define XS_F    (64 * 130)                 // 8320 floats
#define CSD_F2  (128 * 65)                 // 8320 float2
#define SMEM_REQ ((XS_F + CSD_F2 * 2 + 1024) * 4)   // 103936 B

extern __shared__ float sm_dyn[];

__global__ void __launch_bounds__(256, 2)
argmin_kernel(const float* __restrict__ x, const float* __restrict__ cb,
              const float* __restrict__ ema, float* __restrict__ out)
{
    const float DECAYF = 0.999f;
    float*  xs  = sm_dyn;                       // 64*130
    float2* csd = (float2*)(sm_dyn + XS_F);     // [128][65] duplicated pairs
    float*  bsq = sm_dyn + XS_F + CSD_F2 * 2;   // 1024

    const int t  = threadIdx.x;
    const int d  = blockIdx.y;
    const int b0 = blockIdx.x * 128;
    const int blk = d * 4 + blockIdx.x;   // 0..255

    // ---- fused output prep (fire-and-forget, hidden under compute) ----
    {
        float4 z = make_float4(0.f, 0.f, 0.f, 0.f);
        float4* oh4 = (float4*)(out + OH_OFF);
        size_t base = (size_t)blk * (OH_SIZE / 256 / 4);   // 32768 f4 per blk
        #pragma unroll 4
        for (int it = 0; it < 128; ++it)
            oh4[base + t + it * 256] = z;

        const float4* cb4  = (const float4*)cb;
        float4*       ncb4 = (float4*)(out + NCB_OFF);
        size_t cbase = (size_t)blk * (NCB_SIZE / 256 / 4); // 4096 f4 per blk
        #pragma unroll 4
        for (int it = 0; it < 16; ++it) {
            float4 v = cb4[cbase + t + it * 256];
            v.x *= DECAYF; v.y *= DECAYF; v.z *= DECAYF; v.w *= DECAYF;
            ncb4[cbase + t + it * 256] = v;
        }
        if (t < 64) {
            const float4* em4 = (const float4*)ema;
            float4*       ne4 = (float4*)(out + NEMA_OFF);
            size_t eb = (size_t)blk * 64 + t;
            float4 v = em4[eb];
            v.x *= DECAYF; v.y *= DECAYF; v.z *= DECAYF; v.w *= DECAYF;
            ne4[eb] = v;
        }
    }

    // ---- load x tile, transposed into xs[e][row] ----
    #pragma unroll
    for (int it = 0; it < 8; ++it) {
        int idx = t + it * 256;       // 0..2047
        int row = idx >> 4;           // 0..127
        int e4  = (idx & 15) * 4;
        float4 v = *(const float4*)(x + (size_t)(b0 + row) * CWDIM + d * EMB + e4);
        xs[(e4 + 0) * 130 + row] = v.x;
        xs[(e4 + 1) * 130 + row] = v.y;
        xs[(e4 + 2) * 130 + row] = v.z;
        xs[(e4 + 3) * 130 + row] = v.w;
    }

    const float* cbd = cb + (size_t)d * (BOOK * EMB);

    // ---- |c|^2 for all 1024 codes of this d ----
    #pragma unroll
    for (int q = 0; q < 4; ++q) {
        int r = q * 256 + t;
        const float4* cr = (const float4*)(cbd + (size_t)r * EMB);
        float s = 0.f;
        #pragma unroll
        for (int f = 0; f < 16; ++f) {
            float4 v = cr[f];
            s = fmaf(v.x, v.x, s); s = fmaf(v.y, v.y, s);
            s = fmaf(v.z, v.z, s); s = fmaf(v.w, v.w, s);
        }
        bsq[r] = s;
    }

    const int tr = t >> 4, tc = t & 15;
    float bestS[8];
    int   bestI[8];
    #pragma unroll
    for (int m = 0; m < 8; ++m) { bestS[m] = 3.4e38f; bestI[m] = 0; }

    for (int kt = 0; kt < 8; ++kt) {
        __syncthreads();   // protect csd from previous tile's readers
        // load 128 x 64 codebook k-tile as duplicated (c,c) pairs
        #pragma unroll
        for (int it = 0; it < 8; ++it) {
            int idx = t + it * 256;   // 0..2047
            int kk  = idx >> 4;       // 0..127
            int e4  = (idx & 15) * 4;
            float4 v = *(const float4*)(cbd + (size_t)(kt * 128 + kk) * EMB + e4);
            float2* dst = csd + kk * 65 + e4;
            dst[0] = make_float2(v.x, v.x);
            dst[1] = make_float2(v.y, v.y);
            dst[2] = make_float2(v.z, v.z);
            dst[3] = make_float2(v.w, v.w);
        }
        __syncthreads();

        unsigned long long acc[4][8];
        #pragma unroll
        for (int i = 0; i < 4; ++i)
            #pragma unroll
            for (int j = 0; j < 8; ++j) acc[i][j] = 0ull;

        #pragma unroll 2
        for (int e = 0; e < EMB; ++e) {
            unsigned long long a2[4];
            #pragma unroll
            for (int i = 0; i < 4; ++i)
                a2[i] = *(const unsigned long long*)(xs + e * 130 + 2 * (tr + 16 * i));
            #pragma unroll
            for (int j = 0; j < 8; ++j) {
                unsigned long long bb =
                    *(const unsigned long long*)(csd + (tc + 16 * j) * 65 + e);
                #pragma unroll
                for (int i = 0; i < 4; ++i)
                    asm("fma.rn.f32x2 %0, %1, %2, %0;"
                        : "+l"(acc[i][j]) : "l"(a2[i]), "l"(bb));
            }
        }

        // epilogue: score = bsq[k] - 2*dot  (x_sq omitted: constant per row)
        #pragma unroll
        for (int j = 0; j < 8; ++j) {
            int k = kt * 128 + tc + 16 * j;
            float bq = bsq[k];
            #pragma unroll
            for (int i = 0; i < 4; ++i) {
                unsigned int ulo, uhi;
                asm("mov.b64 {%0, %1}, %2;" : "=r"(ulo), "=r"(uhi) : "l"(acc[i][j]));
                float s0 = fmaf(-2.f, __uint_as_float(ulo), bq);
                float s1 = fmaf(-2.f, __uint_as_float(uhi), bq);
                if (s0 < bestS[2 * i])     { bestS[2 * i]     = s0; bestI[2 * i]     = k; }
                if (s1 < bestS[2 * i + 1]) { bestS[2 * i + 1] = s1; bestI[2 * i + 1] = k; }
            }
        }
    }

    // reduce across the 16 tc threads (half-warp), ties -> lowest index
    #pragma unroll
    for (int m = 0; m < 8; ++m) {
        float s  = bestS[m];
        int   ki = bestI[m];
        #pragma unroll
        for (int off = 8; off > 0; off >>= 1) {
            float os = __shfl_down_sync(0xffffffffu, s,  off, 16);
            int   oi = __shfl_down_sync(0xffffffffu, ki, off, 16);
            if (os < s || (os == s && oi < ki)) { s = os; ki = oi; }
        }
        if (tc == 0) {
            int row = 2 * (tr + 16 * (m >> 1)) + (m & 1);
            g_idx[(b0 + row) * DIMC + d] = ki;
        }
    }
}

// ---------------------------------------------------------------------------
// Kernel 2: gather cw, set one_hot ones, EMA scatter-adds.
// One warp per (b,d); lane handles 2 embedding elements.
// ---------------------------------------------------------------------------
__global__ void __launch_bounds__(256)
scatter_kernel(const float* __restrict__ x, const float* __restrict__ cb,
               const float* __restrict__ ema, float* __restrict__ out)
{
    const float GAINF = (float)(1.0 - 0.999);
    const float EPSF  = 1e-6f;
    float* cw   = out + CW_OFF;
    float* oh   = out + OH_OFF;
    float* ncb  = out + NCB_OFF;
    float* nema = out + NEMA_OFF;

    int b    = blockIdx.x;
    int warp = threadIdx.x >> 5;
    int lane = threadIdx.x & 31;

    #pragma unroll
    for (int dd = 0; dd < 8; ++dd) {
        int d = warp * 8 + dd;
        int k = g_idx[b * DIMC + d];
        float g = GAINF / (ema[d * BOOK + k] + EPSF);

        size_t co = ((size_t)d * BOOK + k) * EMB + 2 * lane;
        size_t xo = (size_t)b * CWDIM + d * EMB + 2 * lane;
        float2 c2 = *(const float2*)(cb + co);
        float2 x2 = *(const float2*)(x + xo);

        // cw = x + (c - x): mirror reference fp order exactly
        float2 w;
        w.x = x2.x + (c2.x - x2.x);
        w.y = x2.y + (c2.y - x2.y);
        *(float2*)(cw + xo) = w;

        atomicAdd(ncb + co,     g * x2.x);
        atomicAdd(ncb + co + 1, g * x2.y);

        if (lane == 0) {
            oh[(size_t)b * (DIMC * BOOK) + (size_t)d * BOOK + k] = 1.0f;
            atomicAdd(nema + d * BOOK + k, GAINF);
        }
    }
}

// ---------------------------------------------------------------------------
extern "C" void kernel_launch(void* const* d_in, const int* in_sizes, int n_in,
                              void* d_out, int out_size)
{
    (void)in_sizes; (void)n_in; (void)out_size;
    const float* x   = (const float*)d_in[0];
    const float* cb  = (const float*)d_in[1];
    const float* ema = (const float*)d_in[2];
    float* out = (float*)d_out;

    cudaFuncSetAttribute(argmin_kernel,
                         cudaFuncAttributeMaxDynamicSharedMemorySize, SMEM_REQ);

    dim3 grid(4, 64);
    argmin_kernel<<<grid, 256, SMEM_REQ>>>(x, cb, ema, out);
    scatter_kernel<<<BATCH, 256>>>(x, cb, ema, out);
}

// round 9
// speedup vs baseline: 1.4703x; 1.2171x over previous
#include <cuda_runtime.h>
#include <cuda_fp16.h>
#include <cstdint>

// Problem constants
#define BATCH   512
#define DIMC    64
#define BOOK    1024
#define EMB     64
#define CWDIM   (DIMC * EMB)            // 4096

// Output layout (floats): cw | one_hot | new_codebook | new_ema
#define CW_OFF    0
#define CW_SIZE   (BATCH * CWDIM)
#define OH_OFF    (CW_OFF + CW_SIZE)
#define OH_SIZE   (BATCH * DIMC * BOOK)              // 33,554,432
#define NCB_OFF   (OH_OFF + OH_SIZE)
#define NCB_SIZE  (DIMC * BOOK * EMB)                // 4,194,304
#define NEMA_OFF  (NCB_OFF + NCB_SIZE)
#define NEMA_SIZE (DIMC * BOOK)

#define GAP_TH 1.0f

// Scratch
__device__ __half g_ch[DIMC * BOOK * EMB];   // fp16 codebook, 8.4 MB
__device__ float  g_bsq[DIMC * BOOK];        // exact |c|^2
__device__ uint4  g_cand[BATCH * DIMC];      // approx top-4 keys (dist|k)

static __device__ __forceinline__ float unsortf(unsigned s) {
    unsigned u = (s & 0x80000000u) ? (s & 0x7FFFFFFFu) : ~s;
    return __uint_as_float(u);
}

// insert key into ascending top-4 array
#define INS4(T, KEY) do {                                                   \
    unsigned _k = (KEY);                                                    \
    if (_k < (T)[3]) {                                                      \
        if (_k < (T)[2]) {                                                  \
            (T)[3] = (T)[2];                                                \
            if (_k < (T)[1]) {                                              \
                (T)[2] = (T)[1];                                            \
                if (_k < (T)[0]) { (T)[1] = (T)[0]; (T)[0] = _k; }          \
                else             { (T)[1] = _k; }                           \
            } else { (T)[2] = _k; }                                         \
        } else { (T)[3] = _k; }                                             \
    }                                                                       \
} while (0)

#define HFMA2(acc, a, b)                                                    \
    asm("fma.rn.f16x2 %0, %1, %2, %0;" : "+r"(acc) : "r"(a), "r"(b))

// ---------------------------------------------------------------------------
// Kernel 0: fp16 codebook conversion + exact |c|^2. One warp per code row.
// ---------------------------------------------------------------------------
__global__ void __launch_bounds__(256)
prep_kernel(const float* __restrict__ cb)
{
    int r    = blockIdx.x * 8 + (threadIdx.x >> 5);   // 0..65535 = d*1024+k
    int lane = threadIdx.x & 31;
    float2 v = *(const float2*)(cb + (size_t)r * EMB + lane * 2);
    *(__half2*)(g_ch + (size_t)r * EMB + lane * 2) = __floats2half2_rn(v.x, v.y);
    float s = v.x * v.x + v.y * v.y;
    #pragma unroll
    for (int off = 16; off; off >>= 1)
        s += __shfl_xor_sync(0xffffffffu, s, off);
    if (lane == 0) g_bsq[r] = s;
}

// ---------------------------------------------------------------------------
// Kernel 1: approx distance argmin via HFMA2, CTA = 64 rows x 1024 codes of
// one d. 256 threads, (tr,tc)=(t>>4,t&15); thread tile 4 rows x 4 codes per
// 64-code k-tile (16 tiles). Two phase accumulators per (i,j) -> each fp16
// lane sums only 16 products. Per-thread top-4 keys -> merge -> g_cand.
// Fused one_hot zero + ncb/nema DECAY-init spread across kt iterations.
// ---------------------------------------------------------------------------
__global__ void __launch_bounds__(256)
argmin_kernel(const float* __restrict__ x, const float* __restrict__ cbin,
              const float* __restrict__ ema, float* __restrict__ out)
{
    __shared__ __half2 xs[64 * 34];        // rows stride 34 half2 (136B)
    __shared__ __half2 cs[2][64 * 34];     // double-buffered code tile
    __shared__ float   bsqs[1024];

    const int t  = threadIdx.x;
    const int tr = t >> 4, tc = t & 15;
    const int d  = blockIdx.y;
    const int b0 = blockIdx.x * 64;
    const int blk = d * 8 + blockIdx.x;    // 0..511

    // ---- load x tile as half2 ----
    #pragma unroll
    for (int it = 0; it < 8; ++it) {
        int idx = t + it * 256;            // 0..2047
        int row = idx >> 5, p = idx & 31;
        float2 v = *(const float2*)(x + (size_t)(b0 + row) * CWDIM + d * EMB + 2 * p);
        xs[row * 34 + p] = __floats2half2_rn(v.x, v.y);
    }
    #pragma unroll
    for (int it = 0; it < 4; ++it)
        bsqs[t + it * 256] = g_bsq[d * BOOK + t + it * 256];

    const __half* chd = g_ch + (size_t)d * (BOOK * EMB);

    // prefetch k-tile 0
    {
        #pragma unroll
        for (int q = 0; q < 4; ++q) {
            int idx = t + q * 256;         // 0..1023
            int row = idx >> 4, seg = idx & 15;
            uint2 v = ((const uint2*)(chd + (size_t)row * EMB))[seg];
            *(uint2*)&cs[0][row * 34 + seg * 2] = v;
        }
    }
    __syncthreads();

    unsigned T4[4][4];
    #pragma unroll
    for (int i = 0; i < 4; ++i)
        #pragma unroll
        for (int q = 0; q < 4; ++q) T4[i][q] = 0xFFFFFFFFu;

    for (int kt = 0; kt < 16; ++kt) {
        const int cur = kt & 1;

        // issue LDGs for next tile early
        uint2 nx[4];
        if (kt < 15) {
            #pragma unroll
            for (int q = 0; q < 4; ++q) {
                int idx = t + q * 256;
                int row = idx >> 4, seg = idx & 15;
                nx[q] = ((const uint2*)(chd + (size_t)((kt + 1) * 64 + row) * EMB))[seg];
            }
        }

        // ---- fused output prep slice (fire-and-forget) ----
        {
            float4 z = make_float4(0.f, 0.f, 0.f, 0.f);
            float4* oh4 = (float4*)(out + OH_OFF);
            size_t base = (size_t)blk * 16384 + (size_t)kt * 1024;
            #pragma unroll
            for (int q = 0; q < 4; ++q)
                oh4[base + t + q * 256] = z;
            if (kt < 8) {
                const float4* cb4 = (const float4*)cbin;
                float4* ncb4 = (float4*)(out + NCB_OFF);
                size_t o = (size_t)blk * 2048 + (size_t)kt * 256 + t;
                float4 v = cb4[o];
                v.x *= 0.999f; v.y *= 0.999f; v.z *= 0.999f; v.w *= 0.999f;
                ncb4[o] = v;
            }
            if (kt == 8 && t < 32) {
                const float4* em4 = (const float4*)ema;
                float4* ne4 = (float4*)(out + NEMA_OFF);
                size_t o = (size_t)blk * 32 + t;
                float4 v = em4[o];
                v.x *= 0.999f; v.y *= 0.999f; v.z *= 0.999f; v.w *= 0.999f;
                ne4[o] = v;
            }
        }

        // ---- HFMA2 mainloop: 16 iters x (8 LDS.64 + 16 HFMA2) = 64 MAC/iter
        unsigned acc[4][4][2];
        #pragma unroll
        for (int i = 0; i < 4; ++i)
            #pragma unroll
            for (int j = 0; j < 4; ++j) { acc[i][j][0] = 0u; acc[i][j][1] = 0u; }

        #pragma unroll 4
        for (int p = 0; p < 32; p += 2) {
            uint2 av[4], bv[4];
            #pragma unroll
            for (int i = 0; i < 4; ++i)
                av[i] = *(const uint2*)&xs[(tr + 16 * i) * 34 + p];
            #pragma unroll
            for (int j = 0; j < 4; ++j)
                bv[j] = *(const uint2*)&cs[cur][(tc + 16 * j) * 34 + p];
            #pragma unroll
            for (int i = 0; i < 4; ++i)
                #pragma unroll
                for (int j = 0; j < 4; ++j) {
                    HFMA2(acc[i][j][0], av[i].x, bv[j].x);
                    HFMA2(acc[i][j][1], av[i].y, bv[j].y);
                }
        }

        // ---- epilogue: dist = bsq - 2*dot; insert into top-4 ----
        #pragma unroll
        for (int j = 0; j < 4; ++j) {
            int k = kt * 64 + tc + 16 * j;
            float bq = bsqs[k];
            #pragma unroll
            for (int i = 0; i < 4; ++i) {
                unsigned s2;
                asm("add.rn.f16x2 %0, %1, %2;"
                    : "=r"(s2) : "r"(acc[i][j][0]), "r"(acc[i][j][1]));
                float2 f2 = __half22float2(*(__half2*)&s2);
                float dist = fmaf(-2.f, f2.x + f2.y, bq);
                unsigned u = __float_as_uint(dist);
                unsigned srt = (u & 0x80000000u) ? ~u : (u | 0x80000000u);
                unsigned key = (srt & 0xFFFFFC00u) | (unsigned)k;
                INS4(T4[i], key);
            }
        }

        // store next tile, sync
        if (kt < 15) {
            #pragma unroll
            for (int q = 0; q < 4; ++q) {
                int idx = t + q * 256;
                int row = idx >> 4, seg = idx & 15;
                *(uint2*)&cs[cur ^ 1][row * 34 + seg * 2] = nx[q];
            }
        }
        __syncthreads();
    }

    // ---- merge top-4 across the 16 tc threads (xor offsets stay in-group) --
    #pragma unroll
    for (int off = 1; off <= 8; off <<= 1) {
        #pragma unroll
        for (int i = 0; i < 4; ++i) {
            unsigned r0 = __shfl_xor_sync(0xffffffffu, T4[i][0], off);
            unsigned r1 = __shfl_xor_sync(0xffffffffu, T4[i][1], off);
            unsigned r2 = __shfl_xor_sync(0xffffffffu, T4[i][2], off);
            unsigned r3 = __shfl_xor_sync(0xffffffffu, T4[i][3], off);
            INS4(T4[i], r0); INS4(T4[i], r1); INS4(T4[i], r2); INS4(T4[i], r3);
        }
    }
    if (tc == 0) {
        #pragma unroll
        for (int i = 0; i < 4; ++i) {
            int row = b0 + tr + 16 * i;
            g_cand[(size_t)row * DIMC + d] =
                make_uint4(T4[i][0], T4[i][1], T4[i][2], T4[i][3]);
        }
    }
}

// ---------------------------------------------------------------------------
// Kernel 2: resolve argmin exactly (4-candidate fp32 recompute; full repair
// when approx gap can't certify), then cw gather, one_hot ones, EMA adds.
// One warp per (b,d).
// ---------------------------------------------------------------------------
__global__ void __launch_bounds__(256)
scatter_kernel(const float* __restrict__ x, const float* __restrict__ cb,
               const float* __restrict__ ema, float* __restrict__ out)
{
    const float GAINF = (float)(1.0 - 0.999);
    const float EPSF  = 1e-6f;
    float* cw   = out + CW_OFF;
    float* oh   = out + OH_OFF;
    float* ncb  = out + NCB_OFF;
    float* nema = out + NEMA_OFF;

    int b    = blockIdx.x;
    int warp = threadIdx.x >> 5;
    int lane = threadIdx.x & 31;

    #pragma unroll 1
    for (int dd = 0; dd < 8; ++dd) {
        int d = warp * 8 + dd;
        uint4 cd = g_cand[(size_t)b * DIMC + d];
        int kc[4] = { (int)(cd.x & 1023u), (int)(cd.y & 1023u),
                      (int)(cd.z & 1023u), (int)(cd.w & 1023u) };
        float f1 = unsortf(cd.x & 0xFFFFFC00u);
        float f4 = unsortf(cd.w & 0xFFFFFC00u);
        int k;

        if (f4 - f1 < GAP_TH) {
            // full exact fp32 re-argmin over all 1024 codes
            const float* xr = x + (size_t)b * CWDIM + d * EMB;
            float bd = 3.4e38f;
            int   bk = 0;
            for (int i = 0; i < 32; ++i) {
                int kq = i * 32 + lane;
                const float4* cp = (const float4*)(cb + ((size_t)d * BOOK + kq) * EMB);
                float dot = 0.f;
                #pragma unroll
                for (int e = 0; e < 16; ++e) {
                    float4 c4 = cp[e];
                    const float4 x4 = ((const float4*)xr)[e];
                    dot = fmaf(x4.x, c4.x, dot); dot = fmaf(x4.y, c4.y, dot);
                    dot = fmaf(x4.z, c4.z, dot); dot = fmaf(x4.w, c4.w, dot);
                }
                float dist = fmaf(-2.f, dot, g_bsq[d * BOOK + kq]);
                if (dist < bd) { bd = dist; bk = kq; }
            }
            #pragma unroll
            for (int off = 16; off; off >>= 1) {
                float od = __shfl_xor_sync(0xffffffffu, bd, off);
                int   ok = __shfl_xor_sync(0xffffffffu, bk, off);
                if (od < bd || (od == bd && ok < bk)) { bd = od; bk = ok; }
            }
            k = bk;
        } else {
            // exact distances of the 4 candidates
            int ci = lane >> 3, le = lane & 7;
            const float* cp = cb + ((size_t)d * BOOK + kc[ci]) * EMB;
            const float* xr = x + (size_t)b * CWDIM + d * EMB;
            float p = 0.f;
            #pragma unroll
            for (int e = 0; e < 8; ++e)
                p = fmaf(xr[le + e * 8], cp[le + e * 8], p);
            p += __shfl_xor_sync(0xffffffffu, p, 1);
            p += __shfl_xor_sync(0xffffffffu, p, 2);
            p += __shfl_xor_sync(0xffffffffu, p, 4);
            float dist = fmaf(-2.f, p, g_bsq[d * BOOK + kc[ci]]);
            float dv[4];
            dv[0] = __shfl_sync(0xffffffffu, dist, 0);
            dv[1] = __shfl_sync(0xffffffffu, dist, 8);
            dv[2] = __shfl_sync(0xffffffffu, dist, 16);
            dv[3] = __shfl_sync(0xffffffffu, dist, 24);
            float bd = dv[0]; int bk = kc[0];
            #pragma unroll
            for (int c = 1; c < 4; ++c)
                if (dv[c] < bd || (dv[c] == bd && kc[c] < bk)) { bd = dv[c]; bk = kc[c]; }
            k = bk;
        }

        float g = GAINF / (ema[d * BOOK + k] + EPSF);

        size_t co = ((size_t)d * BOOK + k) * EMB + 2 * lane;
        size_t xo = (size_t)b * CWDIM + d * EMB + 2 * lane;
        float2 c2 = *(const float2*)(cb + co);
        float2 x2 = *(const float2*)(x + xo);

        float2 w;
        w.x = x2.x + (c2.x - x2.x);
        w.y = x2.y + (c2.y - x2.y);
        *(float2*)(cw + xo) = w;

        atomicAdd(ncb + co,     g * x2.x);
        atomicAdd(ncb + co + 1, g * x2.y);

        if (lane == 0) {
            oh[(size_t)b * (DIMC * BOOK) + (size_t)d * BOOK + k] = 1.0f;
            atomicAdd(nema + d * BOOK + k, GAINF);
        }
    }
}

// ---------------------------------------------------------------------------
extern "C" void kernel_launch(void* const* d_in, const int* in_sizes, int n_in,
                              void* d_out, int out_size)
{
    (void)in_sizes; (void)n_in; (void)out_size;
    const float* x   = (const float*)d_in[0];
    const float* cb  = (const float*)d_in[1];
    const float* ema = (const float*)d_in[2];
    float* out = (float*)d_out;

    prep_kernel<<<8192, 256>>>(cb);
    dim3 grid(8, 64);
    argmin_kernel<<<grid, 256>>>(x, cb, ema, out);
    scatter_kernel<<<BATCH, 256>>>(x, cb, ema, out);
}

// round 10
// speedup vs baseline: 1.7870x; 1.2154x over previous
#include <cuda_runtime.h>
#include <cstdint>

// Problem constants
#define BATCH   512
#define DIMC    64
#define BOOK    1024
#define EMB     64
#define CWDIM   (DIMC * EMB)            // 4096

// Output layout (floats): cw | one_hot | new_codebook | new_ema
#define CW_OFF    0
#define CW_SIZE   (BATCH * CWDIM)                    // 2,097,152
#define OH_OFF    (CW_OFF + CW_SIZE)
#define OH_SIZE   (BATCH * DIMC * BOOK)              // 33,554,432
#define NCB_OFF   (OH_OFF + OH_SIZE)
#define NCB_SIZE  (DIMC * BOOK * EMB)                // 4,194,304
#define NEMA_OFF  (NCB_OFF + NCB_SIZE)
#define NEMA_SIZE (DIMC * BOOK)

#define NCTA   296     // exactly 2 CTAs per SM on 148 SMs
#define UNITS  4096    // (d:64) x (row-tile:4 of 128) x (k-tile:16 of 64)

// global argmin keys: (sortable_dist << 32) | k  — atomicMin-merged
__device__ unsigned long long g_key[BATCH * DIMC];

static __device__ __forceinline__ unsigned long long pack2(float v) {
    unsigned long long r;
    asm("mov.b64 %0, {%1, %1};" : "=l"(r) : "r"(__float_as_uint(v)));
    return r;
}

// ---------------------------------------------------------------------------
// Kernel 1: balanced persistent-slice argmin (R1 inner loop verbatim) fused
// with one_hot zero + ncb/nema DECAY-init slices.
// 296 CTAs x 256 threads; CTA i handles units [i*4096/296, (i+1)*4096/296).
// Unit u: blk=u>>4 -> (d=blk>>2, rt=blk&3: rows rt*128..+127); kt=u&15: codes
// kt*64..+63. kt is the minor index, so each CTA reloads xs at most twice.
// SMEM: xs[e][row] 64x130 f32 ; cs[k][e] 64x65 f32 ; bsq[64].
// Thread (tr,tc)=(t>>4,t&15): 4 row-pairs (8 rows) x 4 codes; acc f32x2.
// Cross-CTA merge via atomicMin on g_key.
// ---------------------------------------------------------------------------
#define XS_F   (64 * 130)
#define CS_F   (64 * 65)
#define SMEM_REQ ((XS_F + CS_F + 64) * 4)   // 50,176 B -> 2 CTAs/SM

extern __shared__ float sm_dyn[];

__global__ void __launch_bounds__(256, 2)
argmin_kernel(const float* __restrict__ x, const float* __restrict__ cb,
              const float* __restrict__ ema, float* __restrict__ out)
{
    const float DECAYF = 0.999f;
    float* xs  = sm_dyn;               // 64*130
    float* cs  = sm_dyn + XS_F;        // 64*65
    float* bsq = cs + CS_F;            // 64

    const int t  = threadIdx.x;
    const int tr = t >> 4, tc = t & 15;

    const int u0 = (int)(((long long)blockIdx.x * UNITS) / NCTA);
    const int u1 = (int)(((long long)(blockIdx.x + 1) * UNITS) / NCTA);

    int prevBlk = -1, pd = 0, prt = 0;
    int d = 0, b0 = 0;

    float bestS[8];
    int   bestI[8];

    for (int u = u0; u < u1; ++u) {
        const int blk = u >> 4, kt = u & 15;

        if (blk != prevBlk) {
            // ---- flush previous block's per-thread argmin ----
            if (prevBlk >= 0) {
                #pragma unroll
                for (int m = 0; m < 8; ++m) {
                    float s  = bestS[m];
                    int   ki = bestI[m];
                    #pragma unroll
                    for (int off = 8; off > 0; off >>= 1) {
                        float os = __shfl_down_sync(0xffffffffu, s,  off, 16);
                        int   oi = __shfl_down_sync(0xffffffffu, ki, off, 16);
                        if (os < s || (os == s && oi < ki)) { s = os; ki = oi; }
                    }
                    if (tc == 0) {
                        int row = prt * 128 + 2 * (tr + 16 * (m >> 1)) + (m & 1);
                        unsigned us = __float_as_uint(s);
                        us = (s < 0.f) ? ~us : (us | 0x80000000u);
                        unsigned long long key =
                            ((unsigned long long)us << 32) | (unsigned)ki;
                        atomicMin(&g_key[row * DIMC + pd], key);
                    }
                }
            }
            __syncthreads();   // all FMA readers of xs done before overwrite

            d  = blk >> 2;
            b0 = (blk & 3) * 128;
            pd = d; prt = blk & 3; prevBlk = blk;

            // ---- load x tile, transposed into xs[e][row] ----
            #pragma unroll
            for (int it = 0; it < 8; ++it) {
                int idx = t + it * 256;       // 0..2047
                int row = idx >> 4;           // 0..127
                int e4  = (idx & 15) * 4;
                float4 v = *(const float4*)(x + (size_t)(b0 + row) * CWDIM
                                              + d * EMB + e4);
                xs[(e4 + 0) * 130 + row] = v.x;
                xs[(e4 + 1) * 130 + row] = v.y;
                xs[(e4 + 2) * 130 + row] = v.z;
                xs[(e4 + 3) * 130 + row] = v.w;
            }
            #pragma unroll
            for (int m = 0; m < 8; ++m) { bestS[m] = 3.4e38f; bestI[m] = 0; }
        }

        // ---- fused output prep slice for this unit (fire-and-forget) ----
        {
            float4 z = make_float4(0.f, 0.f, 0.f, 0.f);
            float4* oh4 = (float4*)(out + OH_OFF);
            size_t base = (size_t)u * 2048;       // 2048 f4 per unit
            #pragma unroll
            for (int q = 0; q < 8; ++q)
                oh4[base + t + q * 256] = z;

            const float4* cb4  = (const float4*)cb;
            float4*       ncb4 = (float4*)(out + NCB_OFF);
            size_t co = (size_t)u * 256 + t;      // 256 f4 per unit
            float4 v = cb4[co];
            v.x *= DECAYF; v.y *= DECAYF; v.z *= DECAYF; v.w *= DECAYF;
            ncb4[co] = v;

            if (t < 4) {
                const float4* em4 = (const float4*)ema;
                float4*       ne4 = (float4*)(out + NEMA_OFF);
                size_t eo = (size_t)u * 4 + t;    // 4 f4 per unit
                float4 e = em4[eo];
                e.x *= DECAYF; e.y *= DECAYF; e.z *= DECAYF; e.w *= DECAYF;
                ne4[eo] = e;
            }
        }

        const float* cbd = cb + (size_t)d * (BOOK * EMB);

        __syncthreads();   // cs readers of previous unit done
        // ---- load 64 x 64 codebook k-tile into cs[k][e] (pad 65) ----
        #pragma unroll
        for (int it = 0; it < 4; ++it) {
            int idx = t + it * 256;   // 0..1023
            int kk  = idx >> 4;       // 0..63
            int e4  = (idx & 15) * 4;
            float4 v = *(const float4*)(cbd + (size_t)(kt * 64 + kk) * EMB + e4);
            cs[kk * 65 + e4 + 0] = v.x;
            cs[kk * 65 + e4 + 1] = v.y;
            cs[kk * 65 + e4 + 2] = v.z;
            cs[kk * 65 + e4 + 3] = v.w;
        }
        __syncthreads();
        if (t < 64) {
            float s = 0.f;
            #pragma unroll
            for (int e = 0; e < EMB; ++e) {
                float c = cs[t * 65 + e];
                s = fmaf(c, c, s);
            }
            bsq[t] = s;
        }
        __syncthreads();

        // ---- FMA mainloop (R1 verbatim) ----
        unsigned long long acc[4][4];
        #pragma unroll
        for (int i = 0; i < 4; ++i)
            #pragma unroll
            for (int j = 0; j < 4; ++j) acc[i][j] = 0ull;

        #pragma unroll 4
        for (int e = 0; e < EMB; ++e) {
            unsigned long long a2[4];
            #pragma unroll
            for (int i = 0; i < 4; ++i)
                a2[i] = *(const unsigned long long*)(xs + e * 130
                                                     + 2 * (tr + 16 * i));
            #pragma unroll
            for (int j = 0; j < 4; ++j) {
                unsigned long long bb = pack2(cs[(tc + 16 * j) * 65 + e]);
                #pragma unroll
                for (int i = 0; i < 4; ++i)
                    asm("fma.rn.f32x2 %0, %1, %2, %0;"
                        : "+l"(acc[i][j]) : "l"(a2[i]), "l"(bb));
            }
        }

        // ---- epilogue: score = bsq[k] - 2*dot (x_sq constant per row) ----
        #pragma unroll
        for (int j = 0; j < 4; ++j) {
            int kk = tc + 16 * j;
            int k  = kt * 64 + kk;
            float bq = bsq[kk];
            #pragma unroll
            for (int i = 0; i < 4; ++i) {
                unsigned ulo, uhi;
                asm("mov.b64 {%0, %1}, %2;"
                    : "=r"(ulo), "=r"(uhi) : "l"(acc[i][j]));
                float s0 = fmaf(-2.f, __uint_as_float(ulo), bq);
                float s1 = fmaf(-2.f, __uint_as_float(uhi), bq);
                if (s0 < bestS[2 * i])     { bestS[2 * i]     = s0; bestI[2 * i]     = k; }
                if (s1 < bestS[2 * i + 1]) { bestS[2 * i + 1] = s1; bestI[2 * i + 1] = k; }
            }
        }
    }

    // ---- final flush ----
    if (prevBlk >= 0) {
        #pragma unroll
        for (int m = 0; m < 8; ++m) {
            float s  = bestS[m];
            int   ki = bestI[m];
            #pragma unroll
            for (int off = 8; off > 0; off >>= 1) {
                float os = __shfl_down_sync(0xffffffffu, s,  off, 16);
                int   oi = __shfl_down_sync(0xffffffffu, ki, off, 16);
                if (os < s || (os == s && oi < ki)) { s = os; ki = oi; }
            }
            if (tc == 0) {
                int row = prt * 128 + 2 * (tr + 16 * (m >> 1)) + (m & 1);
                unsigned us = __float_as_uint(s);
                us = (s < 0.f) ? ~us : (us | 0x80000000u);
                unsigned long long key =
                    ((unsigned long long)us << 32) | (unsigned)ki;
                atomicMin(&g_key[row * DIMC + pd], key);
            }
        }
    }
}

// ---------------------------------------------------------------------------
// Kernel 2: gather cw, set one_hot ones, EMA scatter-adds.
// One warp per (b,d); lane handles 2 embedding elements.
// ---------------------------------------------------------------------------
__global__ void __launch_bounds__(256)
scatter_kernel(const float* __restrict__ x, const float* __restrict__ cb,
               const float* __restrict__ ema, float* __restrict__ out)
{
    const float GAINF = (float)(1.0 - 0.999);
    const float EPSF  = 1e-6f;
    float* cw   = out + CW_OFF;
    float* oh   = out + OH_OFF;
    float* ncb  = out + NCB_OFF;
    float* nema = out + NEMA_OFF;

    int b    = blockIdx.x;
    int warp = threadIdx.x >> 5;
    int lane = threadIdx.x & 31;

    #pragma unroll
    for (int dd = 0; dd < 8; ++dd) {
        int d = warp * 8 + dd;
        int k = (int)(unsigned)(g_key[b * DIMC + d] & 0xFFFFFFFFull);
        float g = GAINF / (ema[d * BOOK + k] + EPSF);

        size_t co = ((size_t)d * BOOK + k) * EMB + 2 * lane;
        size_t xo = (size_t)b * CWDIM + d * EMB + 2 * lane;
        float2 c2 = *(const float2*)(cb + co);
        float2 x2 = *(const float2*)(x + xo);

        // cw = x + (c - x): mirror reference fp order exactly
        float2 w;
        w.x = x2.x + (c2.x - x2.x);
        w.y = x2.y + (c2.y - x2.y);
        *(float2*)(cw + xo) = w;

        atomicAdd(ncb + co,     g * x2.x);
        atomicAdd(ncb + co + 1, g * x2.y);

        if (lane == 0) {
            oh[(size_t)b * (DIMC * BOOK) + (size_t)d * BOOK + k] = 1.0f;
            atomicAdd(nema + d * BOOK + k, GAINF);
        }
    }
}

// ---------------------------------------------------------------------------
extern "C" void kernel_launch(void* const* d_in, const int* in_sizes, int n_in,
                              void* d_out, int out_size)
{
    (void)in_sizes; (void)n_in; (void)out_size;
    const float* x   = (const float*)d_in[0];
    const float* cb  = (const float*)d_in[1];
    const float* ema = (const float*)d_in[2];
    float* out = (float*)d_out;

    // reset argmin keys to +inf (graph-capturable memset node)
    void* keyp = nullptr;
    cudaGetSymbolAddress(&keyp, g_key);
    cudaMemsetAsync(keyp, 0xFF, (size_t)BATCH * DIMC * sizeof(unsigned long long));

    cudaFuncSetAttribute(argmin_kernel,
                         cudaFuncAttributeMaxDynamicSharedMemorySize, SMEM_REQ);

    argmin_kernel<<<NCTA, 256, SMEM_REQ>>>(x, cb, ema, out);
    scatter_kernel<<<BATCH, 256>>>(x, cb, ema, out);
}

// round 11
// speedup vs baseline: 2.6951x; 1.5082x over previous
#include <cuda_runtime.h>
#include <cstdint>

// Problem constants
#define BATCH   512
#define DIMC    64
#define BOOK    1024
#define EMB     64
#define CWDIM   (DIMC * EMB)            // 4096

// Output layout (floats): cw | one_hot | new_codebook | new_ema
#define CW_OFF    0
#define CW_SIZE   (BATCH * CWDIM)                    // 2,097,152
#define OH_OFF    (CW_OFF + CW_SIZE)
#define OH_SIZE   (BATCH * DIMC * BOOK)              // 33,554,432
#define NCB_OFF   (OH_OFF + OH_SIZE)
#define NCB_SIZE  (DIMC * BOOK * EMB)                // 4,194,304
#define NEMA_OFF  (NCB_OFF + NCB_SIZE)
#define NEMA_SIZE (DIMC * BOOK)

// global argmin keys: (sortable_dist << 32) | k — atomicMin-merged
__device__ unsigned long long g_key[BATCH * DIMC];

static __device__ __forceinline__ unsigned long long pack2(float v) {
    unsigned long long r;
    asm("mov.b64 %0, {%1, %1};" : "=l"(r) : "r"(__float_as_uint(v)));
    return r;
}

// ---------------------------------------------------------------------------
// Kernel 1: R1's argmin kernel verbatim, with ONLY the k-range split 4-ways
// for load balance (1024 CTAs -> makespan 1.75x vs 2.0x single-CTA time).
//
// Grid: (16, 64) — blockIdx.x = {mt: row tile (4 of 128), kq: k quarter},
// blockIdx.y = d. 256 threads. SMEM identical to R1:
//   xs[e][row]  64 x 130 f32 (transposed x tile)
//   cs[k][e]    64 x 65 f32 (codebook k-tile)
//   bsq[64]
// Thread (tr,tc)=(t>>4,t&15): 4 row-pairs (8 rows) x 4 codes per tile.
// Fused one_hot zero + ncb/nema DECAY-init: each CTA writes its 1/1024
// share upfront (fire-and-forget, hidden under compute).
// Cross-CTA merge via atomicMin on packed sortable key.
// ---------------------------------------------------------------------------
extern __shared__ float sm_dyn[];

__global__ void __launch_bounds__(256, 2)
argmin_kernel(const float* __restrict__ x, const float* __restrict__ cb,
              const float* __restrict__ ema, float* __restrict__ out)
{
    const float DECAYF = 0.999f;
    float* xs  = sm_dyn;              // 64*130
    float* cs  = sm_dyn + 64 * 130;   // 64*65
    float* bsq = cs + 64 * 65;        // 64

    const int t  = threadIdx.x;
    const int mt = blockIdx.x & 3;          // row tile
    const int kq = blockIdx.x >> 2;         // k quarter: tiles kq*4..kq*4+3
    const int d  = blockIdx.y;
    const int b0 = mt * 128;
    const int blk = d * 16 + blockIdx.x;    // 0..1023

    // ---- fused output prep (fire-and-forget stores, hidden under compute) ----
    {
        float4 z = make_float4(0.f, 0.f, 0.f, 0.f);
        float4* oh4 = (float4*)(out + OH_OFF);
        size_t base = (size_t)blk * (OH_SIZE / 1024 / 4);   // 8192 f4 per blk
        #pragma unroll 4
        for (int it = 0; it < 32; ++it)
            oh4[base + t + it * 256] = z;

        const float4* cb4  = (const float4*)cb;
        float4*       ncb4 = (float4*)(out + NCB_OFF);
        size_t cbase = (size_t)blk * (NCB_SIZE / 1024 / 4); // 1024 f4 per blk
        #pragma unroll 4
        for (int it = 0; it < 4; ++it) {
            float4 v = cb4[cbase + t + it * 256];
            v.x *= DECAYF; v.y *= DECAYF; v.z *= DECAYF; v.w *= DECAYF;
            ncb4[cbase + t + it * 256] = v;
        }
        if (t < 16) {
            const float4* em4 = (const float4*)ema;
            float4*       ne4 = (float4*)(out + NEMA_OFF);
            size_t eb = (size_t)blk * 16 + t;              // 16384 f4 total
            float4 v = em4[eb];
            v.x *= DECAYF; v.y *= DECAYF; v.z *= DECAYF; v.w *= DECAYF;
            ne4[eb] = v;
        }
    }

    // ---- load x tile, transposed into xs[e][row] ----
    #pragma unroll
    for (int it = 0; it < 8; ++it) {
        int idx = t + it * 256;       // 0..2047
        int row = idx >> 4;           // 0..127
        int e4  = (idx & 15) * 4;
        float4 v = *(const float4*)(x + (size_t)(b0 + row) * CWDIM + d * EMB + e4);
        xs[(e4 + 0) * 130 + row] = v.x;
        xs[(e4 + 1) * 130 + row] = v.y;
        xs[(e4 + 2) * 130 + row] = v.z;
        xs[(e4 + 3) * 130 + row] = v.w;
    }

    const int tr = t >> 4, tc = t & 15;
    float bestS[8];
    int   bestI[8];
    #pragma unroll
    for (int m = 0; m < 8; ++m) { bestS[m] = 3.4e38f; bestI[m] = 0; }

    const float* cbd = cb + (size_t)d * (BOOK * EMB);

    for (int kt = kq * 4; kt < kq * 4 + 4; ++kt) {
        __syncthreads();   // protect cs/bsq from previous tile's readers
        // load 64 x 64 codebook k-tile into cs[k][e] (pad 65)
        #pragma unroll
        for (int it = 0; it < 4; ++it) {
            int idx = t + it * 256;   // 0..1023
            int kk  = idx >> 4;       // 0..63
            int e4  = (idx & 15) * 4;
            float4 v = *(const float4*)(cbd + (size_t)(kt * 64 + kk) * EMB + e4);
            cs[kk * 65 + e4 + 0] = v.x;
            cs[kk * 65 + e4 + 1] = v.y;
            cs[kk * 65 + e4 + 2] = v.z;
            cs[kk * 65 + e4 + 3] = v.w;
        }
        __syncthreads();
        if (t < 64) {
            float s = 0.f;
            #pragma unroll
            for (int e = 0; e < EMB; ++e) { float c = cs[t * 65 + e]; s = fmaf(c, c, s); }
            bsq[t] = s;
        }
        __syncthreads();

        unsigned long long acc[4][4];
        #pragma unroll
        for (int i = 0; i < 4; ++i)
            #pragma unroll
            for (int j = 0; j < 4; ++j) acc[i][j] = 0ull;

        #pragma unroll 4
        for (int e = 0; e < EMB; ++e) {
            unsigned long long a2[4];
            #pragma unroll
            for (int i = 0; i < 4; ++i)
                a2[i] = *(const unsigned long long*)(xs + e * 130 + 2 * (tr + 16 * i));
            #pragma unroll
            for (int j = 0; j < 4; ++j) {
                unsigned long long bb = pack2(cs[(tc + 16 * j) * 65 + e]);
                #pragma unroll
                for (int i = 0; i < 4; ++i)
                    asm("fma.rn.f32x2 %0, %1, %2, %0;"
                        : "+l"(acc[i][j]) : "l"(a2[i]), "l"(bb));
            }
        }

        // epilogue: score = bsq[k] - 2*dot  (x_sq omitted: constant per row)
        #pragma unroll
        for (int j = 0; j < 4; ++j) {
            int kk = tc + 16 * j;
            int k  = kt * 64 + kk;
            float bq = bsq[kk];
            #pragma unroll
            for (int i = 0; i < 4; ++i) {
                unsigned int ulo, uhi;
                asm("mov.b64 {%0, %1}, %2;" : "=r"(ulo), "=r"(uhi) : "l"(acc[i][j]));
                float s0 = fmaf(-2.f, __uint_as_float(ulo), bq);
                float s1 = fmaf(-2.f, __uint_as_float(uhi), bq);
                if (s0 < bestS[2 * i])     { bestS[2 * i]     = s0; bestI[2 * i]     = k; }
                if (s1 < bestS[2 * i + 1]) { bestS[2 * i + 1] = s1; bestI[2 * i + 1] = k; }
            }
        }
    }

    // reduce across the 16 tc threads (half-warp), ties -> lowest index,
    // then merge across k-quarter CTAs via atomicMin on the sortable key.
    #pragma unroll
    for (int m = 0; m < 8; ++m) {
        float s  = bestS[m];
        int   ki = bestI[m];
        #pragma unroll
        for (int off = 8; off > 0; off >>= 1) {
            float os = __shfl_down_sync(0xffffffffu, s,  off, 16);
            int   oi = __shfl_down_sync(0xffffffffu, ki, off, 16);
            if (os < s || (os == s && oi < ki)) { s = os; ki = oi; }
        }
        if (tc == 0) {
            int row = 2 * (tr + 16 * (m >> 1)) + (m & 1);
            unsigned us = __float_as_uint(s);
            us = (s < 0.f) ? ~us : (us | 0x80000000u);
            unsigned long long key = ((unsigned long long)us << 32) | (unsigned)ki;
            atomicMin(&g_key[(b0 + row) * DIMC + d], key);
        }
    }
}

// ---------------------------------------------------------------------------
// Kernel 2: gather cw, set one_hot ones, EMA scatter-adds.
// One warp per (b,d); lane handles 2 embedding elements.
// ---------------------------------------------------------------------------
__global__ void __launch_bounds__(256)
scatter_kernel(const float* __restrict__ x, const float* __restrict__ cb,
               const float* __restrict__ ema, float* __restrict__ out)
{
    const float GAINF = (float)(1.0 - 0.999);
    const float EPSF  = 1e-6f;
    float* cw   = out + CW_OFF;
    float* oh   = out + OH_OFF;
    float* ncb  = out + NCB_OFF;
    float* nema = out + NEMA_OFF;

    int b    = blockIdx.x;
    int warp = threadIdx.x >> 5;
    int lane = threadIdx.x & 31;

    #pragma unroll
    for (int dd = 0; dd < 8; ++dd) {
        int d = warp * 8 + dd;
        int k = (int)(unsigned)(g_key[b * DIMC + d] & 0xFFFFFFFFull);
        float g = GAINF / (ema[d * BOOK + k] + EPSF);

        size_t co = ((size_t)d * BOOK + k) * EMB + 2 * lane;
        size_t xo = (size_t)b * CWDIM + d * EMB + 2 * lane;
        float2 c2 = *(const float2*)(cb + co);
        float2 x2 = *(const float2*)(x + xo);

        // cw = x + (c - x): mirror reference fp order exactly
        float2 w;
        w.x = x2.x + (c2.x - x2.x);
        w.y = x2.y + (c2.y - x2.y);
        *(float2*)(cw + xo) = w;

        atomicAdd(ncb + co,     g * x2.x);
        atomicAdd(ncb + co + 1, g * x2.y);

        if (lane == 0) {
            oh[(size_t)b * (DIMC * BOOK) + (size_t)d * BOOK + k] = 1.0f;
            atomicAdd(nema + d * BOOK + k, GAINF);
        }
    }
}

// ---------------------------------------------------------------------------
extern "C" void kernel_launch(void* const* d_in, const int* in_sizes, int n_in,
                              void* d_out, int out_size)
{
    (void)in_sizes; (void)n_in; (void)out_size;
    const float* x   = (const float*)d_in[0];
    const float* cb  = (const float*)d_in[1];
    const float* ema = (const float*)d_in[2];
    float* out = (float*)d_out;

    // reset argmin keys to +inf (graph-capturable memset node)
    void* keyp = nullptr;
    cudaGetSymbolAddress(&keyp, g_key);
    cudaMemsetAsync(keyp, 0xFF, (size_t)BATCH * DIMC * sizeof(unsigned long long));

    const int smem = (64 * 130 + 64 * 65 + 64) * (int)sizeof(float);  // 50432 B
    cudaFuncSetAttribute(argmin_kernel,
                         cudaFuncAttributeMaxDynamicSharedMemorySize, smem);

    dim3 grid(16, 64);
    argmin_kernel<<<grid, 256, smem>>>(x, cb, ema, out);
    scatter_kernel<<<BATCH, 256>>>(x, cb, ema, out);
}

// round 12
// speedup vs baseline: 2.7279x; 1.0122x over previous
#include <cuda_runtime.h>
#include <cstdint>

// Problem constants
#define BATCH   512
#define DIMC    64
#define BOOK    1024
#define EMB     64
#define CWDIM   (DIMC * EMB)            // 4096

// Output layout (floats): cw | one_hot | new_codebook | new_ema
#define CW_OFF    0
#define CW_SIZE   (BATCH * CWDIM)                    // 2,097,152
#define OH_OFF    (CW_OFF + CW_SIZE)
#define OH_SIZE   (BATCH * DIMC * BOOK)              // 33,554,432
#define NCB_OFF   (OH_OFF + OH_SIZE)
#define NCB_SIZE  (DIMC * BOOK * EMB)                // 4,194,304
#define NEMA_OFF  (NCB_OFF + NCB_SIZE)
#define NEMA_SIZE (DIMC * BOOK)

// per-(b,d,kq) partial argmin keys: (sortable_dist<<32)|k — plain stores,
// no init needed (every slot written every launch), merged in scatter.
__device__ unsigned long long g_part[BATCH * DIMC * 4];

static __device__ __forceinline__ unsigned long long pack2(float v) {
    unsigned long long r;
    asm("mov.b64 %0, {%1, %1};" : "=l"(r) : "r"(__float_as_uint(v)));
    return r;
}

// ---------------------------------------------------------------------------
// Kernel 1: R11's argmin kernel, unchanged except the cross-CTA merge is now
// a plain store into this CTA's own g_part slot (no memset, no atomics).
//
// Grid: (16, 64) — blockIdx.x = {mt: row tile, kq: k quarter}, blockIdx.y=d.
// 256 threads. SMEM: xs[e][row] 64x130 f32; cs[k][e] 64x65 f32; bsq[64].
// Thread (tr,tc)=(t>>4,t&15): 4 row-pairs (8 rows) x 4 codes per 64-k tile.
// Fused one_hot zero + ncb/nema DECAY-init (1/1024 share per CTA, upfront).
// ---------------------------------------------------------------------------
extern __shared__ float sm_dyn[];

__global__ void __launch_bounds__(256, 2)
argmin_kernel(const float* __restrict__ x, const float* __restrict__ cb,
              const float* __restrict__ ema, float* __restrict__ out)
{
    const float DECAYF = 0.999f;
    float* xs  = sm_dyn;              // 64*130
    float* cs  = sm_dyn + 64 * 130;   // 64*65
    float* bsq = cs + 64 * 65;        // 64

    const int t  = threadIdx.x;
    const int mt = blockIdx.x & 3;          // row tile
    const int kq = blockIdx.x >> 2;         // k quarter: tiles kq*4..kq*4+3
    const int d  = blockIdx.y;
    const int b0 = mt * 128;
    const int blk = d * 16 + blockIdx.x;    // 0..1023

    // ---- fused output prep (fire-and-forget stores, hidden under compute) ----
    {
        float4 z = make_float4(0.f, 0.f, 0.f, 0.f);
        float4* oh4 = (float4*)(out + OH_OFF);
        size_t base = (size_t)blk * (OH_SIZE / 1024 / 4);   // 8192 f4 per blk
        #pragma unroll 4
        for (int it = 0; it < 32; ++it)
            oh4[base + t + it * 256] = z;

        const float4* cb4  = (const float4*)cb;
        float4*       ncb4 = (float4*)(out + NCB_OFF);
        size_t cbase = (size_t)blk * (NCB_SIZE / 1024 / 4); // 1024 f4 per blk
        #pragma unroll 4
        for (int it = 0; it < 4; ++it) {
            float4 v = cb4[cbase + t + it * 256];
            v.x *= DECAYF; v.y *= DECAYF; v.z *= DECAYF; v.w *= DECAYF;
            ncb4[cbase + t + it * 256] = v;
        }
        if (t < 16) {
            const float4* em4 = (const float4*)ema;
            float4*       ne4 = (float4*)(out + NEMA_OFF);
            size_t eb = (size_t)blk * 16 + t;              // 16384 f4 total
            float4 v = em4[eb];
            v.x *= DECAYF; v.y *= DECAYF; v.z *= DECAYF; v.w *= DECAYF;
            ne4[eb] = v;
        }
    }

    // ---- load x tile, transposed into xs[e][row] ----
    #pragma unroll
    for (int it = 0; it < 8; ++it) {
        int idx = t + it * 256;       // 0..2047
        int row = idx >> 4;           // 0..127
        int e4  = (idx & 15) * 4;
        float4 v = *(const float4*)(x + (size_t)(b0 + row) * CWDIM + d * EMB + e4);
        xs[(e4 + 0) * 130 + row] = v.x;
        xs[(e4 + 1) * 130 + row] = v.y;
        xs[(e4 + 2) * 130 + row] = v.z;
        xs[(e4 + 3) * 130 + row] = v.w;
    }

    const int tr = t >> 4, tc = t & 15;
    float bestS[8];
    int   bestI[8];
    #pragma unroll
    for (int m = 0; m < 8; ++m) { bestS[m] = 3.4e38f; bestI[m] = 0; }

    const float* cbd = cb + (size_t)d * (BOOK * EMB);

    for (int kt = kq * 4; kt < kq * 4 + 4; ++kt) {
        __syncthreads();   // protect cs/bsq from previous tile's readers
        // load 64 x 64 codebook k-tile into cs[k][e] (pad 65)
        #pragma unroll
        for (int it = 0; it < 4; ++it) {
            int idx = t + it * 256;   // 0..1023
            int kk  = idx >> 4;       // 0..63
            int e4  = (idx & 15) * 4;
            float4 v = *(const float4*)(cbd + (size_t)(kt * 64 + kk) * EMB + e4);
            cs[kk * 65 + e4 + 0] = v.x;
            cs[kk * 65 + e4 + 1] = v.y;
            cs[kk * 65 + e4 + 2] = v.z;
            cs[kk * 65 + e4 + 3] = v.w;
        }
        __syncthreads();
        if (t < 64) {
            float s = 0.f;
            #pragma unroll
            for (int e = 0; e < EMB; ++e) { float c = cs[t * 65 + e]; s = fmaf(c, c, s); }
            bsq[t] = s;
        }
        __syncthreads();

        unsigned long long acc[4][4];
        #pragma unroll
        for (int i = 0; i < 4; ++i)
            #pragma unroll
            for (int j = 0; j < 4; ++j) acc[i][j] = 0ull;

        #pragma unroll 4
        for (int e = 0; e < EMB; ++e) {
            unsigned long long a2[4];
            #pragma unroll
            for (int i = 0; i < 4; ++i)
                a2[i] = *(const unsigned long long*)(xs + e * 130 + 2 * (tr + 16 * i));
            #pragma unroll
            for (int j = 0; j < 4; ++j) {
                unsigned long long bb = pack2(cs[(tc + 16 * j) * 65 + e]);
                #pragma unroll
                for (int i = 0; i < 4; ++i)
                    asm("fma.rn.f32x2 %0, %1, %2, %0;"
                        : "+l"(acc[i][j]) : "l"(a2[i]), "l"(bb));
            }
        }

        // epilogue: score = bsq[k] - 2*dot  (x_sq omitted: constant per row)
        #pragma unroll
        for (int j = 0; j < 4; ++j) {
            int kk = tc + 16 * j;
            int k  = kt * 64 + kk;
            float bq = bsq[kk];
            #pragma unroll
            for (int i = 0; i < 4; ++i) {
                unsigned int ulo, uhi;
                asm("mov.b64 {%0, %1}, %2;" : "=r"(ulo), "=r"(uhi) : "l"(acc[i][j]));
                float s0 = fmaf(-2.f, __uint_as_float(ulo), bq);
                float s1 = fmaf(-2.f, __uint_as_float(uhi), bq);
                if (s0 < bestS[2 * i])     { bestS[2 * i]     = s0; bestI[2 * i]     = k; }
                if (s1 < bestS[2 * i + 1]) { bestS[2 * i + 1] = s1; bestI[2 * i + 1] = k; }
            }
        }
    }

    // reduce across the 16 tc threads (half-warp), ties -> lowest index,
    // then plain-store this k-quarter's key into g_part.
    #pragma unroll
    for (int m = 0; m < 8; ++m) {
        float s  = bestS[m];
        int   ki = bestI[m];
        #pragma unroll
        for (int off = 8; off > 0; off >>= 1) {
            float os = __shfl_down_sync(0xffffffffu, s,  off, 16);
            int   oi = __shfl_down_sync(0xffffffffu, ki, off, 16);
            if (os < s || (os == s && oi < ki)) { s = os; ki = oi; }
        }
        if (tc == 0) {
            int row = 2 * (tr + 16 * (m >> 1)) + (m & 1);
            unsigned us = __float_as_uint(s);
            us = (s < 0.f) ? ~us : (us | 0x80000000u);
            unsigned long long key = ((unsigned long long)us << 32) | (unsigned)ki;
            g_part[(((size_t)(b0 + row) * DIMC) + d) * 4 + kq] = key;
        }
    }
}

// ---------------------------------------------------------------------------
// Kernel 2: merge 4 partial keys -> k, gather cw, one_hot ones, EMA adds.
// Grid 2048 x 128: one warp per 4 (b,d) pairs; all 4 key-merges issued
// up-front for MLP before the dependent bodies.
// ---------------------------------------------------------------------------
__global__ void __launch_bounds__(128)
scatter_kernel(const float* __restrict__ x, const float* __restrict__ cb,
               const float* __restrict__ ema, float* __restrict__ out)
{
    const float GAINF = (float)(1.0 - 0.999);
    const float EPSF  = 1e-6f;
    float* cw   = out + CW_OFF;
    float* oh   = out + OH_OFF;
    float* ncb  = out + NCB_OFF;
    float* nema = out + NEMA_OFF;

    int w    = blockIdx.x * 4 + (threadIdx.x >> 5);   // 0..8191
    int lane = threadIdx.x & 31;

    // prefetch + merge all 4 pairs' keys (independent chains)
    int kk[4], bb[4], dp[4];
    float gg[4];
    #pragma unroll
    for (int q = 0; q < 4; ++q) {
        int pair = w * 4 + q;            // 0..32767
        int b = pair >> 6, d = pair & 63;
        const unsigned long long* pp = &g_part[(size_t)pair * 4];
        unsigned long long k0 = pp[0], k1 = pp[1], k2 = pp[2], k3 = pp[3];
        unsigned long long key = min(min(k0, k1), min(k2, k3));
        kk[q] = (int)(unsigned)(key & 0xFFFFFFFFull);
        bb[q] = b; dp[q] = d;
    }
    #pragma unroll
    for (int q = 0; q < 4; ++q)
        gg[q] = GAINF / (ema[dp[q] * BOOK + kk[q]] + EPSF);

    #pragma unroll
    for (int q = 0; q < 4; ++q) {
        int b = bb[q], d = dp[q], k = kk[q];
        size_t co = ((size_t)d * BOOK + k) * EMB + 2 * lane;
        size_t xo = (size_t)b * CWDIM + d * EMB + 2 * lane;
        float2 c2 = *(const float2*)(cb + co);
        float2 x2 = *(const float2*)(x + xo);

        // cw = x + (c - x): mirror reference fp order exactly
        float2 wv;
        wv.x = x2.x + (c2.x - x2.x);
        wv.y = x2.y + (c2.y - x2.y);
        *(float2*)(cw + xo) = wv;

        atomicAdd(ncb + co,     gg[q] * x2.x);
        atomicAdd(ncb + co + 1, gg[q] * x2.y);

        if (lane == 0) {
            oh[(size_t)b * (DIMC * BOOK) + (size_t)d * BOOK + k] = 1.0f;
            atomicAdd(nema + d * BOOK + k, GAINF);
        }
    }
}

// ---------------------------------------------------------------------------
extern "C" void kernel_launch(void* const* d_in, const int* in_sizes, int n_in,
                              void* d_out, int out_size)
{
    (void)in_sizes; (void)n_in; (void)out_size;
    const float* x   = (const float*)d_in[0];
    const float* cb  = (const float*)d_in[1];
    const float* ema = (const float*)d_in[2];
    float* out = (float*)d_out;

    const int smem = (64 * 130 + 64 * 65 + 64) * (int)sizeof(float);  // 50432 B
    cudaFuncSetAttribute(argmin_kernel,
                         cudaFuncAttributeMaxDynamicSharedMemorySize, smem);

    dim3 grid(16, 64);
    argmin_kernel<<<grid, 256, smem>>>(x, cb, ema, out);
    scatter_kernel<<<2048, 128>>>(x, cb, ema, out);
}

// round 13
// speedup vs baseline: 2.7399x; 1.0044x over previous
#include <cuda_runtime.h>
#include <cstdint>

// Problem constants
#define BATCH   512
#define DIMC    64
#define BOOK    1024
#define EMB     64
#define CWDIM   (DIMC * EMB)            // 4096

// Output layout (floats): cw | one_hot | new_codebook | new_ema
#define CW_OFF    0
#define CW_SIZE   (BATCH * CWDIM)                    // 2,097,152
#define OH_OFF    (CW_OFF + CW_SIZE)
#define OH_SIZE   (BATCH * DIMC * BOOK)              // 33,554,432
#define NCB_OFF   (OH_OFF + OH_SIZE)
#define NCB_SIZE  (DIMC * BOOK * EMB)                // 4,194,304
#define NEMA_OFF  (NCB_OFF + NCB_SIZE)
#define NEMA_SIZE (DIMC * BOOK)

// per-(b,d,kq) partial argmin keys: (sortable_dist<<32)|k — plain stores,
// no init needed (every slot written every launch), merged in scatter.
__device__ unsigned long long g_part[BATCH * DIMC * 4];

static __device__ __forceinline__ unsigned long long pack2(float v) {
    unsigned long long r;
    asm("mov.b64 %0, {%1, %1};" : "=l"(r) : "r"(__float_as_uint(v)));
    return r;
}

// ---------------------------------------------------------------------------
// Kernel 1: unchanged from R12 (argmin at 98% of the scalar-FMA floor).
// Grid: (16, 64) — blockIdx.x = {mt: row tile, kq: k quarter}, blockIdx.y=d.
// SMEM: xs[e][row] 64x130 f32; cs[k][e] 64x65 f32; bsq[64].
// Thread (tr,tc)=(t>>4,t&15): 4 row-pairs (8 rows) x 4 codes per 64-k tile.
// Fused one_hot zero + ncb/nema DECAY-init (1/1024 share per CTA, upfront).
// ---------------------------------------------------------------------------
extern __shared__ float sm_dyn[];

__global__ void __launch_bounds__(256, 2)
argmin_kernel(const float* __restrict__ x, const float* __restrict__ cb,
              const float* __restrict__ ema, float* __restrict__ out)
{
    const float DECAYF = 0.999f;
    float* xs  = sm_dyn;              // 64*130
    float* cs  = sm_dyn + 64 * 130;   // 64*65
    float* bsq = cs + 64 * 65;        // 64

    const int t  = threadIdx.x;
    const int mt = blockIdx.x & 3;          // row tile
    const int kq = blockIdx.x >> 2;         // k quarter: tiles kq*4..kq*4+3
    const int d  = blockIdx.y;
    const int b0 = mt * 128;
    const int blk = d * 16 + blockIdx.x;    // 0..1023

    // ---- fused output prep (fire-and-forget stores, hidden under compute) ----
    {
        float4 z = make_float4(0.f, 0.f, 0.f, 0.f);
        float4* oh4 = (float4*)(out + OH_OFF);
        size_t base = (size_t)blk * (OH_SIZE / 1024 / 4);   // 8192 f4 per blk
        #pragma unroll 4
        for (int it = 0; it < 32; ++it)
            oh4[base + t + it * 256] = z;

        const float4* cb4  = (const float4*)cb;
        float4*       ncb4 = (float4*)(out + NCB_OFF);
        size_t cbase = (size_t)blk * (NCB_SIZE / 1024 / 4); // 1024 f4 per blk
        #pragma unroll 4
        for (int it = 0; it < 4; ++it) {
            float4 v = cb4[cbase + t + it * 256];
            v.x *= DECAYF; v.y *= DECAYF; v.z *= DECAYF; v.w *= DECAYF;
            ncb4[cbase + t + it * 256] = v;
        }
        if (t < 16) {
            const float4* em4 = (const float4*)ema;
            float4*       ne4 = (float4*)(out + NEMA_OFF);
            size_t eb = (size_t)blk * 16 + t;              // 16384 f4 total
            float4 v = em4[eb];
            v.x *= DECAYF; v.y *= DECAYF; v.z *= DECAYF; v.w *= DECAYF;
            ne4[eb] = v;
        }
    }

    // ---- load x tile, transposed into xs[e][row] ----
    #pragma unroll
    for (int it = 0; it < 8; ++it) {
        int idx = t + it * 256;       // 0..2047
        int row = idx >> 4;           // 0..127
        int e4  = (idx & 15) * 4;
        float4 v = *(const float4*)(x + (size_t)(b0 + row) * CWDIM + d * EMB + e4);
        xs[(e4 + 0) * 130 + row] = v.x;
        xs[(e4 + 1) * 130 + row] = v.y;
        xs[(e4 + 2) * 130 + row] = v.z;
        xs[(e4 + 3) * 130 + row] = v.w;
    }

    const int tr = t >> 4, tc = t & 15;
    float bestS[8];
    int   bestI[8];
    #pragma unroll
    for (int m = 0; m < 8; ++m) { bestS[m] = 3.4e38f; bestI[m] = 0; }

    const float* cbd = cb + (size_t)d * (BOOK * EMB);

    for (int kt = kq * 4; kt < kq * 4 + 4; ++kt) {
        __syncthreads();   // protect cs/bsq from previous tile's readers
        // load 64 x 64 codebook k-tile into cs[k][e] (pad 65)
        #pragma unroll
        for (int it = 0; it < 4; ++it) {
            int idx = t + it * 256;   // 0..1023
            int kk  = idx >> 4;       // 0..63
            int e4  = (idx & 15) * 4;
            float4 v = *(const float4*)(cbd + (size_t)(kt * 64 + kk) * EMB + e4);
            cs[kk * 65 + e4 + 0] = v.x;
            cs[kk * 65 + e4 + 1] = v.y;
            cs[kk * 65 + e4 + 2] = v.z;
            cs[kk * 65 + e4 + 3] = v.w;
        }
        __syncthreads();
        if (t < 64) {
            float s = 0.f;
            #pragma unroll
            for (int e = 0; e < EMB; ++e) { float c = cs[t * 65 + e]; s = fmaf(c, c, s); }
            bsq[t] = s;
        }
        __syncthreads();

        unsigned long long acc[4][4];
        #pragma unroll
        for (int i = 0; i < 4; ++i)
            #pragma unroll
            for (int j = 0; j < 4; ++j) acc[i][j] = 0ull;

        #pragma unroll 4
        for (int e = 0; e < EMB; ++e) {
            unsigned long long a2[4];
            #pragma unroll
            for (int i = 0; i < 4; ++i)
                a2[i] = *(const unsigned long long*)(xs + e * 130 + 2 * (tr + 16 * i));
            #pragma unroll
            for (int j = 0; j < 4; ++j) {
                unsigned long long bb = pack2(cs[(tc + 16 * j) * 65 + e]);
                #pragma unroll
                for (int i = 0; i < 4; ++i)
                    asm("fma.rn.f32x2 %0, %1, %2, %0;"
                        : "+l"(acc[i][j]) : "l"(a2[i]), "l"(bb));
            }
        }

        // epilogue: score = bsq[k] - 2*dot  (x_sq omitted: constant per row)
        #pragma unroll
        for (int j = 0; j < 4; ++j) {
            int kk = tc + 16 * j;
            int k  = kt * 64 + kk;
            float bq = bsq[kk];
            #pragma unroll
            for (int i = 0; i < 4; ++i) {
                unsigned int ulo, uhi;
                asm("mov.b64 {%0, %1}, %2;" : "=r"(ulo), "=r"(uhi) : "l"(acc[i][j]));
                float s0 = fmaf(-2.f, __uint_as_float(ulo), bq);
                float s1 = fmaf(-2.f, __uint_as_float(uhi), bq);
                if (s0 < bestS[2 * i])     { bestS[2 * i]     = s0; bestI[2 * i]     = k; }
                if (s1 < bestS[2 * i + 1]) { bestS[2 * i + 1] = s1; bestI[2 * i + 1] = k; }
            }
        }
    }

    // reduce across the 16 tc threads (half-warp), ties -> lowest index,
    // then plain-store this k-quarter's key into g_part.
    #pragma unroll
    for (int m = 0; m < 8; ++m) {
        float s  = bestS[m];
        int   ki = bestI[m];
        #pragma unroll
        for (int off = 8; off > 0; off >>= 1) {
            float os = __shfl_down_sync(0xffffffffu, s,  off, 16);
            int   oi = __shfl_down_sync(0xffffffffu, ki, off, 16);
            if (os < s || (os == s && oi < ki)) { s = os; ki = oi; }
        }
        if (tc == 0) {
            int row = 2 * (tr + 16 * (m >> 1)) + (m & 1);
            unsigned us = __float_as_uint(s);
            us = (s < 0.f) ? ~us : (us | 0x80000000u);
            unsigned long long key = ((unsigned long long)us << 32) | (unsigned)ki;
            g_part[(((size_t)(b0 + row) * DIMC) + d) * 4 + kq] = key;
        }
    }
}

// ---------------------------------------------------------------------------
// Kernel 2 (v3): ONE (b,d) pair per warp. Lanes 0..3 fetch the 4 partial
// keys in parallel; 2x shfl.xor min-reduce (sortable keys keep lowest-k
// tie-break); broadcast k; all lanes load the same ema word (1-sector
// broadcast); then gather cw, one_hot one, EMA adds. 32768 warps.
// ---------------------------------------------------------------------------
__global__ void __launch_bounds__(256)
scatter_kernel(const float* __restrict__ x, const float* __restrict__ cb,
               const float* __restrict__ ema, float* __restrict__ out)
{
    const float GAINF = (float)(1.0 - 0.999);
    const float EPSF  = 1e-6f;
    float* cw   = out + CW_OFF;
    float* oh   = out + OH_OFF;
    float* ncb  = out + NCB_OFF;
    float* nema = out + NEMA_OFF;

    const int w    = blockIdx.x * 8 + (threadIdx.x >> 5);   // 0..32767 = b*64+d
    const int lane = threadIdx.x & 31;
    const int b = w >> 6, d = w & 63;

    // lane-parallel key merge
    unsigned long long key = 0xFFFFFFFFFFFFFFFFull;
    if (lane < 4) key = g_part[(size_t)w * 4 + lane];
    {
        unsigned long long o;
        o = __shfl_xor_sync(0xffffffffu, key, 1); key = min(key, o);
        o = __shfl_xor_sync(0xffffffffu, key, 2); key = min(key, o);
    }
    const int k = (int)(unsigned)(__shfl_sync(0xffffffffu, key, 0) & 0xFFFFFFFFull);

    const float g = GAINF / (ema[d * BOOK + k] + EPSF);

    size_t co = ((size_t)d * BOOK + k) * EMB + 2 * lane;
    size_t xo = (size_t)b * CWDIM + d * EMB + 2 * lane;
    float2 c2 = *(const float2*)(cb + co);
    float2 x2 = *(const float2*)(x + xo);

    // cw = x + (c - x): mirror reference fp order exactly
    float2 wv;
    wv.x = x2.x + (c2.x - x2.x);
    wv.y = x2.y + (c2.y - x2.y);
    *(float2*)(cw + xo) = wv;

    atomicAdd(ncb + co,     g * x2.x);
    atomicAdd(ncb + co + 1, g * x2.y);

    if (lane == 0) {
        oh[(size_t)b * (DIMC * BOOK) + (size_t)d * BOOK + k] = 1.0f;
        atomicAdd(nema + d * BOOK + k, GAINF);
    }
}

// ---------------------------------------------------------------------------
extern "C" void kernel_launch(void* const* d_in, const int* in_sizes, int n_in,
                              void* d_out, int out_size)
{
    (void)in_sizes; (void)n_in; (void)out_size;
    const float* x   = (const float*)d_in[0];
    const float* cb  = (const float*)d_in[1];
    const float* ema = (const float*)d_in[2];
    float* out = (float*)d_out;

    const int smem = (64 * 130 + 64 * 65 + 64) * (int)sizeof(float);  // 50432 B
    cudaFuncSetAttribute(argmin_kernel,
                         cudaFuncAttributeMaxDynamicSharedMemorySize, smem);

    dim3 grid(16, 64);
    argmin_kernel<<<grid, 256, smem>>>(x, cb, ema, out);
    scatter_kernel<<<4096, 256>>>(x, cb, ema, out);
}